// round 12
// baseline (speedup 1.0000x reference)
#include <cuda_runtime.h>
#include <cuda_fp16.h>
#include <cuda_bf16.h>

// Problem constants
#define BB   16
#define NN   1029
#define HH   16
#define HD   64
#define DD   1024
#define MM   (BB * NN)          // 16464
#define PREFIX 5                // N - NP
#define TOTAL  (MM * DD)        // 16859136

// Scratch (allocation-free rule: use __device__ globals)
__device__ float g_Q  [TOTAL];
__device__ float g_K  [TOTAL];
__device__ float g_V  [TOTAL];
__device__ float g_CTX[TOTAL];

__device__ __forceinline__ void mma_f16(
    float& c0, float& c1, float& c2, float& c3,
    unsigned a0, unsigned a1, unsigned a2, unsigned a3,
    unsigned b0, unsigned b1)
{
    asm volatile(
        "mma.sync.aligned.m16n8k16.row.col.f32.f16.f16.f32 "
        "{%0,%1,%2,%3}, {%4,%5,%6,%7}, {%8,%9}, {%0,%1,%2,%3};\n"
        : "+f"(c0), "+f"(c1), "+f"(c2), "+f"(c3)
        : "r"(a0), "r"(a1), "r"(a2), "r"(a3), "r"(b0), "r"(b1));
}

// ---------------------------------------------------------------------------
// FP16 tensor-core GEMM NT: C[m,n] = sum_k A[m,k] * W[n,k] + bias[n]
// (fp32 in/out, half operands, fp32 accumulate; 11 mantissa bits = tf32)
// 128x128 block tile, k-chunk 32, 256 threads (8 warps), warp tile 64x32.
// mma m16n8k16: 2 k-steps per chunk.  Smem stride 40 halves: fragment
// addresses (20*g + q + 8*ks words) hit all 32 banks -> conflict-free.
// MODE 0: plain row-major store.  MODE 1: fused RoPE + transpose store.
// ---------------------------------------------------------------------------
#define KH   40
#define CPAD 132
#define GEMM_SMEM (128 * CPAD * 4)   // epilogue staging dominates (67584 B)

template <int MODE>
__global__ __launch_bounds__(256) void gemm_f16(
    const float* __restrict__ A, const float* __restrict__ W,
    const float* __restrict__ bias, float* __restrict__ C, int M,
    const float* __restrict__ sinp, const float* __restrict__ cosp)
{
    extern __shared__ __align__(16) unsigned char smem_raw[];
    __half* As = (__half*)smem_raw;            // 128 x KH
    __half* Ws = As + 128 * KH;                // 128 x KH

    const int tid  = threadIdx.x;
    const int warp = tid >> 5;
    const int lane = tid & 31;
    const int g    = lane >> 2;   // 0..7
    const int q    = lane & 3;    // 0..3
    const int wm   = warp >> 2;   // 0..1
    const int wn   = warp & 3;    // 0..3
    const int row0 = blockIdx.y * 128;
    const int col0 = blockIdx.x * 128;

    float acc[4][4][4];
    #pragma unroll
    for (int mt = 0; mt < 4; mt++)
        #pragma unroll
        for (int nt = 0; nt < 4; nt++)
            #pragma unroll
            for (int i = 0; i < 4; i++) acc[mt][nt][i] = 0.f;

    int lrow[4], lk[4];
    #pragma unroll
    for (int j = 0; j < 4; j++) {
        int idx = tid + j * 256;
        lrow[j] = idx >> 3;          // 0..127
        lk[j]   = (idx & 7) * 4;     // 0..28 (k offset within 32-chunk)
    }

    const float4 z4 = make_float4(0.f, 0.f, 0.f, 0.f);
    float4 pa[4], pw[4];
    #pragma unroll
    for (int j = 0; j < 4; j++) {
        int r = row0 + lrow[j];
        pa[j] = (r < M) ? *(const float4*)(A + (long long)r * DD + lk[j]) : z4;
        pw[j] = *(const float4*)(W + (long long)(col0 + lrow[j]) * DD + lk[j]);
    }

    for (int chunk = 0; chunk < DD / 32; chunk++) {
        #pragma unroll
        for (int j = 0; j < 4; j++) {
            __half2* as = (__half2*)&As[lrow[j] * KH + lk[j]];
            as[0] = __floats2half2_rn(pa[j].x, pa[j].y);
            as[1] = __floats2half2_rn(pa[j].z, pa[j].w);
            __half2* ws = (__half2*)&Ws[lrow[j] * KH + lk[j]];
            ws[0] = __floats2half2_rn(pw[j].x, pw[j].y);
            ws[1] = __floats2half2_rn(pw[j].z, pw[j].w);
        }
        __syncthreads();

        if (chunk + 1 < DD / 32) {
            int kb = (chunk + 1) * 32;
            #pragma unroll
            for (int j = 0; j < 4; j++) {
                int r = row0 + lrow[j];
                pa[j] = (r < M) ? *(const float4*)(A + (long long)r * DD + kb + lk[j]) : z4;
                pw[j] = *(const float4*)(W + (long long)(col0 + lrow[j]) * DD + kb + lk[j]);
            }
        }

        #pragma unroll
        for (int ks = 0; ks < 2; ks++) {
            const int kc = ks * 16 + 2 * q;
            unsigned af[4][4], bf[4][2];
            #pragma unroll
            for (int mt = 0; mt < 4; mt++) {
                int row = wm * 64 + mt * 16 + g;
                af[mt][0] = *(const unsigned*)&As[row * KH + kc];
                af[mt][1] = *(const unsigned*)&As[(row + 8) * KH + kc];
                af[mt][2] = *(const unsigned*)&As[row * KH + kc + 8];
                af[mt][3] = *(const unsigned*)&As[(row + 8) * KH + kc + 8];
            }
            #pragma unroll
            for (int nt = 0; nt < 4; nt++) {
                int col = wn * 32 + nt * 8 + g;
                bf[nt][0] = *(const unsigned*)&Ws[col * KH + kc];
                bf[nt][1] = *(const unsigned*)&Ws[col * KH + kc + 8];
            }
            #pragma unroll
            for (int mt = 0; mt < 4; mt++)
                #pragma unroll
                for (int nt = 0; nt < 4; nt++)
                    mma_f16(acc[mt][nt][0], acc[mt][nt][1],
                            acc[mt][nt][2], acc[mt][nt][3],
                            af[mt][0], af[mt][1], af[mt][2], af[mt][3],
                            bf[nt][0], bf[nt][1]);
        }
        __syncthreads();
    }

    if (MODE == 0) {
        #pragma unroll
        for (int mt = 0; mt < 4; mt++) {
            int r0 = row0 + wm * 64 + mt * 16 + g;
            int r1 = r0 + 8;
            #pragma unroll
            for (int nt = 0; nt < 4; nt++) {
                int c = col0 + wn * 32 + nt * 8 + 2 * q;
                float bx = bias[c], by = bias[c + 1];
                if (r0 < M) {
                    float2 v = make_float2(acc[mt][nt][0] + bx, acc[mt][nt][1] + by);
                    *(float2*)(C + (long long)r0 * DD + c) = v;
                }
                if (r1 < M) {
                    float2 v = make_float2(acc[mt][nt][2] + bx, acc[mt][nt][3] + by);
                    *(float2*)(C + (long long)r1 * DD + c) = v;
                }
            }
        }
    } else {
        // fused epilogue: stage (bias applied), then RoPE + transpose store
        float* Cs = (float*)smem_raw;   // 128 x CPAD
        #pragma unroll
        for (int mt = 0; mt < 4; mt++) {
            int lr0 = wm * 64 + mt * 16 + g;
            int lr1 = lr0 + 8;
            #pragma unroll
            for (int nt = 0; nt < 4; nt++) {
                int lc = wn * 32 + nt * 8 + 2 * q;
                float bx = bias[col0 + lc], by = bias[col0 + lc + 1];
                *(float2*)&Cs[lr0 * CPAD + lc] =
                    make_float2(acc[mt][nt][0] + bx, acc[mt][nt][1] + by);
                *(float2*)&Cs[lr1 * CPAD + lc] =
                    make_float2(acc[mt][nt][2] + bx, acc[mt][nt][3] + by);
            }
        }
        __syncthreads();

        #pragma unroll
        for (int i = 0; i < 16; i++) {
            int idx = tid + i * 256;
            int row = idx >> 5;             // 0..127
            int c4  = (idx & 31) * 4;       // 0..124
            int R = row0 + row;
            if (R >= M) continue;
            int b = R / NN;
            int t = R - b * NN;
            int gcol = col0 + c4;
            int h = gcol >> 6;
            int d = gcol & 63;

            float4 x = *(float4*)&Cs[row * CPAD + c4];
            float4 v = x;
            if (t >= PREFIX) {
                int pos = t - PREFIX;
                float4 cc = *(const float4*)(cosp + pos * HD + d);
                float4 ss = *(const float4*)(sinp + pos * HD + d);
                float4 xo = *(float4*)&Cs[row * CPAD + (c4 ^ 32)];
                if (d < 32) { xo.x = -xo.x; xo.y = -xo.y; xo.z = -xo.z; xo.w = -xo.w; }
                v.x = x.x * cc.x + xo.x * ss.x;
                v.y = x.y * cc.y + xo.y * ss.y;
                v.z = x.z * cc.z + xo.z * ss.z;
                v.w = x.w * cc.w + xo.w * ss.w;
            }
            *(float4*)(C + (((long long)(b * HH + h)) * NN + t) * HD + d) = v;
        }
    }
}

// ---------------------------------------------------------------------------
// FP16 tensor-core flash attention.
// Q,K: [B,H,N,HD].  V: [B,N,H*HD].  CTX: [B,N,H*HD].
// 256 threads (8 warps), 128-query tile, 64-kv tiles, 2 CTAs/SM.
// ---------------------------------------------------------------------------
#define HST 72
#define OST 68
#define FA_SMEM (27648 * 2 + 256 * 4)   // 56320 B

__global__ __launch_bounds__(256, 2) void flash_attn_tc(
    const float* __restrict__ Q, const float* __restrict__ K,
    const float* __restrict__ Vy, float* __restrict__ CTX)
{
    extern __shared__ __half sm_h[];
    __half* Qs = sm_h;                  // 128 x HST
    __half* Ks = Qs + 128 * HST;        // 64 x HST  (kv x d)
    __half* Vs = Ks + 64 * HST;         // 64 x HST  (kv x d)
    __half* Ps = Vs + 64 * HST;         // 128 x HST (q x kv)
    float* scl  = (float*)(sm_h + 27648);   // 128
    float* linv = scl + 128;                // 128

    const int q0 = blockIdx.x * 128;
    const int h  = blockIdx.y;
    const int b  = blockIdx.z;
    const long long baseQ = ((long long)(b * HH + h)) * NN * HD;
    const int tid  = threadIdx.x;
    const int warp = tid >> 5;
    const int lane = tid & 31;
    const int g    = lane >> 2;
    const int q    = lane & 3;
    const int sr0  = warp * 16 + g;       // S-phase q rows
    const int sr1  = sr0 + 8;
    const int d0   = (warp & 3) * 16;     // PV d rows
    const int qb   = (warp >> 2) * 64;    // PV q cols

    const int lm_kv = ((lane >> 4) & 1) * 8 + (lane & 7);
    const int lm_d  = d0 + ((lane >> 3) & 1) * 8;

    // load Q tile (scaled by HD^-0.5), fp32 -> half2
    #pragma unroll
    for (int i = 0; i < 8; i++) {
        int idx = tid + i * 256;
        int row = idx >> 4, c4 = (idx & 15) * 4;
        int r = q0 + row;
        float4 v = (r < NN) ? *(const float4*)(Q + baseQ + (long long)r * HD + c4)
                            : make_float4(0.f, 0.f, 0.f, 0.f);
        __half2* p = (__half2*)&Qs[row * HST + c4];
        p[0] = __floats2half2_rn(v.x * 0.125f, v.y * 0.125f);
        p[1] = __floats2half2_rn(v.z * 0.125f, v.w * 0.125f);
    }

    float m0 = -1e30f, m1 = -1e30f, l0 = 0.f, l1 = 0.f;
    float oacc[8][4];
    #pragma unroll
    for (int nt = 0; nt < 8; nt++)
        #pragma unroll
        for (int i = 0; i < 4; i++) oacc[nt][i] = 0.f;

    for (int k0 = 0; k0 < NN; k0 += 64) {
        __syncthreads();
        #pragma unroll
        for (int i = 0; i < 4; i++) {
            int idx = tid + i * 256;
            int j = idx >> 4, c4 = (idx & 15) * 4;
            int kv = k0 + j;
            float4 kvec, vvec;
            if (kv < NN) {
                kvec = *(const float4*)(K + baseQ + (long long)kv * HD + c4);
                vvec = *(const float4*)(Vy + ((long long)(b * NN + kv)) * DD + h * HD + c4);
            } else {
                kvec = make_float4(0.f, 0.f, 0.f, 0.f);
                vvec = kvec;
            }
            __half2* pk = (__half2*)&Ks[j * HST + c4];
            pk[0] = __floats2half2_rn(kvec.x, kvec.y);
            pk[1] = __floats2half2_rn(kvec.z, kvec.w);
            __half2* pv = (__half2*)&Vs[j * HST + c4];
            pv[0] = __floats2half2_rn(vvec.x, vvec.y);
            pv[1] = __floats2half2_rn(vvec.z, vvec.w);
        }
        __syncthreads();

        // ---- S = Q @ K^T ----
        float sacc[8][4];
        #pragma unroll
        for (int nt = 0; nt < 8; nt++)
            #pragma unroll
            for (int i = 0; i < 4; i++) sacc[nt][i] = 0.f;

        #pragma unroll
        for (int ks = 0; ks < 4; ks++) {
            const int kc = ks * 16 + 2 * q;
            unsigned a0 = *(const unsigned*)&Qs[sr0 * HST + kc];
            unsigned a1 = *(const unsigned*)&Qs[sr1 * HST + kc];
            unsigned a2 = *(const unsigned*)&Qs[sr0 * HST + kc + 8];
            unsigned a3 = *(const unsigned*)&Qs[sr1 * HST + kc + 8];
            #pragma unroll
            for (int nt = 0; nt < 8; nt++) {
                const __half* kr = &Ks[(nt * 8 + g) * HST + kc];
                unsigned b0 = *(const unsigned*)kr;
                unsigned b1 = *(const unsigned*)(kr + 8);
                mma_f16(sacc[nt][0], sacc[nt][1], sacc[nt][2], sacc[nt][3],
                        a0, a1, a2, a3, b0, b1);
            }
        }

        if (k0 + 64 > NN) {
            #pragma unroll
            for (int nt = 0; nt < 8; nt++) {
                int c = k0 + nt * 8 + 2 * q;
                if (c >= NN)     { sacc[nt][0] = -1e30f; sacc[nt][2] = -1e30f; }
                if (c + 1 >= NN) { sacc[nt][1] = -1e30f; sacc[nt][3] = -1e30f; }
            }
        }

        // online softmax
        float t0 = -1e30f, t1 = -1e30f;
        #pragma unroll
        for (int nt = 0; nt < 8; nt++) {
            t0 = fmaxf(t0, fmaxf(sacc[nt][0], sacc[nt][1]));
            t1 = fmaxf(t1, fmaxf(sacc[nt][2], sacc[nt][3]));
        }
        t0 = fmaxf(t0, __shfl_xor_sync(0xffffffffu, t0, 1));
        t0 = fmaxf(t0, __shfl_xor_sync(0xffffffffu, t0, 2));
        t1 = fmaxf(t1, __shfl_xor_sync(0xffffffffu, t1, 1));
        t1 = fmaxf(t1, __shfl_xor_sync(0xffffffffu, t1, 2));
        float mn0 = fmaxf(m0, t0), mn1 = fmaxf(m1, t1);
        float sc0 = __expf(m0 - mn0), sc1 = __expf(m1 - mn1);
        m0 = mn0; m1 = mn1;

        float ls0 = 0.f, ls1 = 0.f;
        #pragma unroll
        for (int nt = 0; nt < 8; nt++) {
            float p0 = __expf(sacc[nt][0] - mn0);
            float p1 = __expf(sacc[nt][1] - mn0);
            float p2 = __expf(sacc[nt][2] - mn1);
            float p3 = __expf(sacc[nt][3] - mn1);
            ls0 += p0 + p1;
            ls1 += p2 + p3;
            *(__half2*)&Ps[sr0 * HST + nt * 8 + 2 * q] = __floats2half2_rn(p0, p1);
            *(__half2*)&Ps[sr1 * HST + nt * 8 + 2 * q] = __floats2half2_rn(p2, p3);
        }
        ls0 += __shfl_xor_sync(0xffffffffu, ls0, 1);
        ls0 += __shfl_xor_sync(0xffffffffu, ls0, 2);
        ls1 += __shfl_xor_sync(0xffffffffu, ls1, 1);
        ls1 += __shfl_xor_sync(0xffffffffu, ls1, 2);
        l0 = l0 * sc0 + ls0;
        l1 = l1 * sc1 + ls1;
        if (q == 0) { scl[sr0] = sc0; scl[sr1] = sc1; }
        __syncthreads();

        #pragma unroll
        for (int nt = 0; nt < 8; nt++) {
            float s0 = scl[qb + nt * 8 + 2 * q];
            float s1 = scl[qb + nt * 8 + 2 * q + 1];
            oacc[nt][0] *= s0; oacc[nt][1] *= s1;
            oacc[nt][2] *= s0; oacc[nt][3] *= s1;
        }
        // ---- PV: O^T += V^T @ P^T ----
        #pragma unroll
        for (int ks = 0; ks < 4; ks++) {
            unsigned a0, a1, a2, a3;
            {
                const __half* src = &Vs[(ks * 16 + lm_kv) * HST + lm_d];
                unsigned saddr = (unsigned)__cvta_generic_to_shared(src);
                asm volatile(
                    "ldmatrix.sync.aligned.m8n8.x4.trans.shared.b16 "
                    "{%0,%1,%2,%3}, [%4];"
                    : "=r"(a0), "=r"(a1), "=r"(a2), "=r"(a3) : "r"(saddr));
            }
            const int kc = ks * 16 + 2 * q;
            #pragma unroll
            for (int nt = 0; nt < 8; nt++) {
                const __half* pr = &Ps[(qb + nt * 8 + g) * HST + kc];
                unsigned b0 = *(const unsigned*)pr;
                unsigned b1 = *(const unsigned*)(pr + 8);
                mma_f16(oacc[nt][0], oacc[nt][1], oacc[nt][2], oacc[nt][3],
                        a0, a1, a2, a3, b0, b1);
            }
        }
    }

    if (q == 0) { linv[sr0] = 1.f / l0; linv[sr1] = 1.f / l1; }
    __syncthreads();

    float* Osm = (float*)sm_h;   // 128 x OST floats
    #pragma unroll
    for (int nt = 0; nt < 8; nt++) {
        int qc = qb + nt * 8 + 2 * q;
        float i0 = linv[qc], i1 = linv[qc + 1];
        Osm[qc * OST + d0 + g]           = oacc[nt][0] * i0;
        Osm[(qc + 1) * OST + d0 + g]     = oacc[nt][1] * i1;
        Osm[qc * OST + d0 + g + 8]       = oacc[nt][2] * i0;
        Osm[(qc + 1) * OST + d0 + g + 8] = oacc[nt][3] * i1;
    }
    __syncthreads();

    #pragma unroll
    for (int i = 0; i < 8; i++) {
        int idx = tid + i * 256;
        int row = idx >> 4, c4 = (idx & 15) * 4;
        int r = q0 + row;
        if (r < NN) {
            float4 v = *(float4*)&Osm[row * OST + c4];
            *(float4*)(CTX + ((long long)(b * NN + r)) * DD + h * HD + c4) = v;
        }
    }
}

// ---------------------------------------------------------------------------
extern "C" void kernel_launch(void* const* d_in, const int* in_sizes, int n_in,
                              void* d_out, int out_size)
{
    const float* X    = (const float*)d_in[0];
    const float* sinp = (const float*)d_in[1];
    const float* cosp = (const float*)d_in[2];
    const float* Wq   = (const float*)d_in[3];
    const float* bq   = (const float*)d_in[4];
    const float* Wk   = (const float*)d_in[5];
    const float* bk   = (const float*)d_in[6];
    const float* Wv   = (const float*)d_in[7];
    const float* bv   = (const float*)d_in[8];
    const float* Wo   = (const float*)d_in[9];
    const float* bo   = (const float*)d_in[10];
    float* OUT = (float*)d_out;

    float *Qb, *Kb, *Vb, *CTX;
    cudaGetSymbolAddress((void**)&Qb,  g_Q);
    cudaGetSymbolAddress((void**)&Kb,  g_K);
    cudaGetSymbolAddress((void**)&Vb,  g_V);
    cudaGetSymbolAddress((void**)&CTX, g_CTX);

    cudaFuncSetAttribute(gemm_f16<0>,
                         cudaFuncAttributeMaxDynamicSharedMemorySize, GEMM_SMEM);
    cudaFuncSetAttribute(gemm_f16<1>,
                         cudaFuncAttributeMaxDynamicSharedMemorySize, GEMM_SMEM);
    cudaFuncSetAttribute(flash_attn_tc,
                         cudaFuncAttributeMaxDynamicSharedMemorySize, FA_SMEM);

    dim3 ggrid(DD / 128, (MM + 127) / 128);
    dim3 gblk(256);

    // Q/K projections with fused RoPE+transpose -> [B,H,N,HD]
    gemm_f16<1><<<ggrid, gblk, GEMM_SMEM>>>(X, Wq, bq, Qb, MM, sinp, cosp);
    gemm_f16<1><<<ggrid, gblk, GEMM_SMEM>>>(X, Wk, bk, Kb, MM, sinp, cosp);
    // V projection (stays in [B,N,H*HD]; attention reads it directly)
    gemm_f16<0><<<ggrid, gblk, GEMM_SMEM>>>(X, Wv, bv, Vb, MM, sinp, cosp);

    // fp16 tensor-core attention
    dim3 agrid((NN + 127) / 128, HH, BB);   // (9,16,16)
    flash_attn_tc<<<agrid, 256, FA_SMEM>>>(Qb, Kb, Vb, CTX);

    // output projection straight into d_out
    gemm_f16<0><<<ggrid, gblk, GEMM_SMEM>>>(CTX, Wo, bo, OUT, MM, sinp, cosp);
}

// round 13
// speedup vs baseline: 1.5755x; 1.5755x over previous
#include <cuda_runtime.h>
#include <cuda_fp16.h>
#include <cuda_bf16.h>

// Problem constants
#define BB   16
#define NN   1029
#define HH   16
#define HD   64
#define DD   1024
#define MM   (BB * NN)          // 16464
#define PREFIX 5                // N - NP
#define TOTAL  (MM * DD)        // 16859136

// Scratch (allocation-free rule: use __device__ globals)
__device__ float g_Q  [TOTAL];
__device__ float g_K  [TOTAL];
__device__ float g_V  [TOTAL];
__device__ float g_CTX[TOTAL];

__device__ __forceinline__ void mma_f16(
    float& c0, float& c1, float& c2, float& c3,
    unsigned a0, unsigned a1, unsigned a2, unsigned a3,
    unsigned b0, unsigned b1)
{
    asm volatile(
        "mma.sync.aligned.m16n8k16.row.col.f32.f16.f16.f32 "
        "{%0,%1,%2,%3}, {%4,%5,%6,%7}, {%8,%9}, {%0,%1,%2,%3};\n"
        : "+f"(c0), "+f"(c1), "+f"(c2), "+f"(c3)
        : "r"(a0), "r"(a1), "r"(a2), "r"(a3), "r"(b0), "r"(b1));
}

// ---------------------------------------------------------------------------
// FP16 tensor-core GEMM NT: C[m,n] = sum_k A[m,k] * W[n,k] + bias[n]
// (fp32 in/out, half operands, fp32 accumulate)
// 128x128 block tile, k-chunk 32, 256 threads (8 warps), warp tile 64x32.
// DOUBLE-BUFFERED smem stages: one __syncthreads per chunk; gmem preload
// for chunk c+2 issued while computing chunk c.
// MODE 0: plain row-major store.  MODE 1: fused RoPE + transpose store.
// ---------------------------------------------------------------------------
#define KH    40
#define STG   (128 * KH)            // halves per tile stage
#define CPAD  132
#define GEMM_SMEM0 (4 * STG * 2)            // 40960 B (2 stages A + W)
#define GEMM_SMEM1 (128 * CPAD * 4)         // 67584 B (epilogue staging)

template <int MODE>
__global__ __launch_bounds__(256) void gemm_f16(
    const float* __restrict__ A, const float* __restrict__ W,
    const float* __restrict__ bias, float* __restrict__ C, int M,
    const float* __restrict__ sinp, const float* __restrict__ cosp)
{
    extern __shared__ __align__(16) unsigned char smem_raw[];
    __half* Abuf = (__half*)smem_raw;       // 2 x 128 x KH
    __half* Wbuf = Abuf + 2 * STG;          // 2 x 128 x KH

    const int tid  = threadIdx.x;
    const int warp = tid >> 5;
    const int lane = tid & 31;
    const int g    = lane >> 2;   // 0..7
    const int q    = lane & 3;    // 0..3
    const int wm   = warp >> 2;   // 0..1
    const int wn   = warp & 3;    // 0..3
    const int row0 = blockIdx.y * 128;
    const int col0 = blockIdx.x * 128;

    float acc[4][4][4];
    #pragma unroll
    for (int mt = 0; mt < 4; mt++)
        #pragma unroll
        for (int nt = 0; nt < 4; nt++)
            #pragma unroll
            for (int i = 0; i < 4; i++) acc[mt][nt][i] = 0.f;

    int lrow[4], lk[4];
    #pragma unroll
    for (int j = 0; j < 4; j++) {
        int idx = tid + j * 256;
        lrow[j] = idx >> 3;          // 0..127
        lk[j]   = (idx & 7) * 4;     // 0..28
    }
    const bool arow_ok[4] = {
        row0 + lrow[0] < M, row0 + lrow[1] < M,
        row0 + lrow[2] < M, row0 + lrow[3] < M };
    const float* Ap[4];
    const float* Wp[4];
    #pragma unroll
    for (int j = 0; j < 4; j++) {
        Ap[j] = A + (long long)(row0 + lrow[j]) * DD + lk[j];
        Wp[j] = W + (long long)(col0 + lrow[j]) * DD + lk[j];
    }

    const float4 z4 = make_float4(0.f, 0.f, 0.f, 0.f);
    float4 pa[4], pw[4];

    // ---- pipeline prologue: load c0, store stage0, sync, preload c1 ----
    #pragma unroll
    for (int j = 0; j < 4; j++) {
        pa[j] = arow_ok[j] ? *(const float4*)(Ap[j]) : z4;
        pw[j] = *(const float4*)(Wp[j]);
    }
    #pragma unroll
    for (int j = 0; j < 4; j++) {
        __half2* as = (__half2*)&Abuf[lrow[j] * KH + lk[j]];
        as[0] = __floats2half2_rn(pa[j].x, pa[j].y);
        as[1] = __floats2half2_rn(pa[j].z, pa[j].w);
        __half2* ws = (__half2*)&Wbuf[lrow[j] * KH + lk[j]];
        ws[0] = __floats2half2_rn(pw[j].x, pw[j].y);
        ws[1] = __floats2half2_rn(pw[j].z, pw[j].w);
    }
    __syncthreads();
    #pragma unroll
    for (int j = 0; j < 4; j++) {
        pa[j] = arow_ok[j] ? *(const float4*)(Ap[j] + 32) : z4;
        pw[j] = *(const float4*)(Wp[j] + 32);
    }

    for (int c = 0; c < DD / 32; c++) {
        const __half* Asm = Abuf + (c & 1) * STG;
        const __half* Wsm = Wbuf + (c & 1) * STG;

        // compute chunk c (overlaps outstanding gmem loads for c+1)
        #pragma unroll
        for (int ks = 0; ks < 2; ks++) {
            const int kc = ks * 16 + 2 * q;
            unsigned af[4][4], bf[4][2];
            #pragma unroll
            for (int mt = 0; mt < 4; mt++) {
                int row = wm * 64 + mt * 16 + g;
                af[mt][0] = *(const unsigned*)&Asm[row * KH + kc];
                af[mt][1] = *(const unsigned*)&Asm[(row + 8) * KH + kc];
                af[mt][2] = *(const unsigned*)&Asm[row * KH + kc + 8];
                af[mt][3] = *(const unsigned*)&Asm[(row + 8) * KH + kc + 8];
            }
            #pragma unroll
            for (int nt = 0; nt < 4; nt++) {
                int col = wn * 32 + nt * 8 + g;
                bf[nt][0] = *(const unsigned*)&Wsm[col * KH + kc];
                bf[nt][1] = *(const unsigned*)&Wsm[col * KH + kc + 8];
            }
            #pragma unroll
            for (int mt = 0; mt < 4; mt++)
                #pragma unroll
                for (int nt = 0; nt < 4; nt++)
                    mma_f16(acc[mt][nt][0], acc[mt][nt][1],
                            acc[mt][nt][2], acc[mt][nt][3],
                            af[mt][0], af[mt][1], af[mt][2], af[mt][3],
                            bf[nt][0], bf[nt][1]);
        }

        // store preloaded chunk c+1 into the other stage
        if (c + 1 < DD / 32) {
            __half* Ad = Abuf + ((c + 1) & 1) * STG;
            __half* Wd = Wbuf + ((c + 1) & 1) * STG;
            #pragma unroll
            for (int j = 0; j < 4; j++) {
                __half2* as = (__half2*)&Ad[lrow[j] * KH + lk[j]];
                as[0] = __floats2half2_rn(pa[j].x, pa[j].y);
                as[1] = __floats2half2_rn(pa[j].z, pa[j].w);
                __half2* ws = (__half2*)&Wd[lrow[j] * KH + lk[j]];
                ws[0] = __floats2half2_rn(pw[j].x, pw[j].y);
                ws[1] = __floats2half2_rn(pw[j].z, pw[j].w);
            }
        }
        // issue gmem loads for chunk c+2
        if (c + 2 < DD / 32) {
            int kb = (c + 2) * 32;
            #pragma unroll
            for (int j = 0; j < 4; j++) {
                pa[j] = arow_ok[j] ? *(const float4*)(Ap[j] + kb) : z4;
                pw[j] = *(const float4*)(Wp[j] + kb);
            }
        }
        __syncthreads();
    }

    if (MODE == 0) {
        #pragma unroll
        for (int mt = 0; mt < 4; mt++) {
            int r0 = row0 + wm * 64 + mt * 16 + g;
            int r1 = r0 + 8;
            #pragma unroll
            for (int nt = 0; nt < 4; nt++) {
                int c = col0 + wn * 32 + nt * 8 + 2 * q;
                float bx = bias[c], by = bias[c + 1];
                if (r0 < M) {
                    float2 v = make_float2(acc[mt][nt][0] + bx, acc[mt][nt][1] + by);
                    *(float2*)(C + (long long)r0 * DD + c) = v;
                }
                if (r1 < M) {
                    float2 v = make_float2(acc[mt][nt][2] + bx, acc[mt][nt][3] + by);
                    *(float2*)(C + (long long)r1 * DD + c) = v;
                }
            }
        }
    } else {
        // fused epilogue: stage (bias applied), then RoPE + transpose store
        float* Cs = (float*)smem_raw;   // 128 x CPAD
        #pragma unroll
        for (int mt = 0; mt < 4; mt++) {
            int lr0 = wm * 64 + mt * 16 + g;
            int lr1 = lr0 + 8;
            #pragma unroll
            for (int nt = 0; nt < 4; nt++) {
                int lc = wn * 32 + nt * 8 + 2 * q;
                float bx = bias[col0 + lc], by = bias[col0 + lc + 1];
                *(float2*)&Cs[lr0 * CPAD + lc] =
                    make_float2(acc[mt][nt][0] + bx, acc[mt][nt][1] + by);
                *(float2*)&Cs[lr1 * CPAD + lc] =
                    make_float2(acc[mt][nt][2] + bx, acc[mt][nt][3] + by);
            }
        }
        __syncthreads();

        #pragma unroll
        for (int i = 0; i < 16; i++) {
            int idx = tid + i * 256;
            int row = idx >> 5;             // 0..127
            int c4  = (idx & 31) * 4;       // 0..124
            int R = row0 + row;
            if (R >= M) continue;
            int b = R / NN;
            int t = R - b * NN;
            int gcol = col0 + c4;
            int h = gcol >> 6;
            int d = gcol & 63;

            float4 x = *(float4*)&Cs[row * CPAD + c4];
            float4 v = x;
            if (t >= PREFIX) {
                int pos = t - PREFIX;
                float4 cc = *(const float4*)(cosp + pos * HD + d);
                float4 ss = *(const float4*)(sinp + pos * HD + d);
                float4 xo = *(float4*)&Cs[row * CPAD + (c4 ^ 32)];
                if (d < 32) { xo.x = -xo.x; xo.y = -xo.y; xo.z = -xo.z; xo.w = -xo.w; }
                v.x = x.x * cc.x + xo.x * ss.x;
                v.y = x.y * cc.y + xo.y * ss.y;
                v.z = x.z * cc.z + xo.z * ss.z;
                v.w = x.w * cc.w + xo.w * ss.w;
            }
            *(float4*)(C + (((long long)(b * HH + h)) * NN + t) * HD + d) = v;
        }
    }
}

// ---------------------------------------------------------------------------
// FP16 tensor-core flash attention.
// Q,K: [B,H,N,HD].  V: [B,N,H*HD].  CTX: [B,N,H*HD].
// 256 threads (8 warps), 128-query tile, 64-kv tiles, 2 CTAs/SM.
// ---------------------------------------------------------------------------
#define HST 72
#define OST 68
#define FA_SMEM (27648 * 2 + 256 * 4)   // 56320 B

__global__ __launch_bounds__(256, 2) void flash_attn_tc(
    const float* __restrict__ Q, const float* __restrict__ K,
    const float* __restrict__ Vy, float* __restrict__ CTX)
{
    extern __shared__ __half sm_h[];
    __half* Qs = sm_h;                  // 128 x HST
    __half* Ks = Qs + 128 * HST;        // 64 x HST  (kv x d)
    __half* Vs = Ks + 64 * HST;         // 64 x HST  (kv x d)
    __half* Ps = Vs + 64 * HST;         // 128 x HST (q x kv)
    float* scl  = (float*)(sm_h + 27648);   // 128
    float* linv = scl + 128;                // 128

    const int q0 = blockIdx.x * 128;
    const int h  = blockIdx.y;
    const int b  = blockIdx.z;
    const long long baseQ = ((long long)(b * HH + h)) * NN * HD;
    const int tid  = threadIdx.x;
    const int warp = tid >> 5;
    const int lane = tid & 31;
    const int g    = lane >> 2;
    const int q    = lane & 3;
    const int sr0  = warp * 16 + g;
    const int sr1  = sr0 + 8;
    const int d0   = (warp & 3) * 16;
    const int qb   = (warp >> 2) * 64;

    const int lm_kv = ((lane >> 4) & 1) * 8 + (lane & 7);
    const int lm_d  = d0 + ((lane >> 3) & 1) * 8;

    #pragma unroll
    for (int i = 0; i < 8; i++) {
        int idx = tid + i * 256;
        int row = idx >> 4, c4 = (idx & 15) * 4;
        int r = q0 + row;
        float4 v = (r < NN) ? *(const float4*)(Q + baseQ + (long long)r * HD + c4)
                            : make_float4(0.f, 0.f, 0.f, 0.f);
        __half2* p = (__half2*)&Qs[row * HST + c4];
        p[0] = __floats2half2_rn(v.x * 0.125f, v.y * 0.125f);
        p[1] = __floats2half2_rn(v.z * 0.125f, v.w * 0.125f);
    }

    float m0 = -1e30f, m1 = -1e30f, l0 = 0.f, l1 = 0.f;
    float oacc[8][4];
    #pragma unroll
    for (int nt = 0; nt < 8; nt++)
        #pragma unroll
        for (int i = 0; i < 4; i++) oacc[nt][i] = 0.f;

    for (int k0 = 0; k0 < NN; k0 += 64) {
        __syncthreads();
        #pragma unroll
        for (int i = 0; i < 4; i++) {
            int idx = tid + i * 256;
            int j = idx >> 4, c4 = (idx & 15) * 4;
            int kv = k0 + j;
            float4 kvec, vvec;
            if (kv < NN) {
                kvec = *(const float4*)(K + baseQ + (long long)kv * HD + c4);
                vvec = *(const float4*)(Vy + ((long long)(b * NN + kv)) * DD + h * HD + c4);
            } else {
                kvec = make_float4(0.f, 0.f, 0.f, 0.f);
                vvec = kvec;
            }
            __half2* pk = (__half2*)&Ks[j * HST + c4];
            pk[0] = __floats2half2_rn(kvec.x, kvec.y);
            pk[1] = __floats2half2_rn(kvec.z, kvec.w);
            __half2* pv = (__half2*)&Vs[j * HST + c4];
            pv[0] = __floats2half2_rn(vvec.x, vvec.y);
            pv[1] = __floats2half2_rn(vvec.z, vvec.w);
        }
        __syncthreads();

        // ---- S = Q @ K^T ----
        float sacc[8][4];
        #pragma unroll
        for (int nt = 0; nt < 8; nt++)
            #pragma unroll
            for (int i = 0; i < 4; i++) sacc[nt][i] = 0.f;

        #pragma unroll
        for (int ks = 0; ks < 4; ks++) {
            const int kc = ks * 16 + 2 * q;
            unsigned a0 = *(const unsigned*)&Qs[sr0 * HST + kc];
            unsigned a1 = *(const unsigned*)&Qs[sr1 * HST + kc];
            unsigned a2 = *(const unsigned*)&Qs[sr0 * HST + kc + 8];
            unsigned a3 = *(const unsigned*)&Qs[sr1 * HST + kc + 8];
            #pragma unroll
            for (int nt = 0; nt < 8; nt++) {
                const __half* kr = &Ks[(nt * 8 + g) * HST + kc];
                unsigned b0 = *(const unsigned*)kr;
                unsigned b1 = *(const unsigned*)(kr + 8);
                mma_f16(sacc[nt][0], sacc[nt][1], sacc[nt][2], sacc[nt][3],
                        a0, a1, a2, a3, b0, b1);
            }
        }

        if (k0 + 64 > NN) {
            #pragma unroll
            for (int nt = 0; nt < 8; nt++) {
                int c = k0 + nt * 8 + 2 * q;
                if (c >= NN)     { sacc[nt][0] = -1e30f; sacc[nt][2] = -1e30f; }
                if (c + 1 >= NN) { sacc[nt][1] = -1e30f; sacc[nt][3] = -1e30f; }
            }
        }

        // online softmax
        float t0 = -1e30f, t1 = -1e30f;
        #pragma unroll
        for (int nt = 0; nt < 8; nt++) {
            t0 = fmaxf(t0, fmaxf(sacc[nt][0], sacc[nt][1]));
            t1 = fmaxf(t1, fmaxf(sacc[nt][2], sacc[nt][3]));
        }
        t0 = fmaxf(t0, __shfl_xor_sync(0xffffffffu, t0, 1));
        t0 = fmaxf(t0, __shfl_xor_sync(0xffffffffu, t0, 2));
        t1 = fmaxf(t1, __shfl_xor_sync(0xffffffffu, t1, 1));
        t1 = fmaxf(t1, __shfl_xor_sync(0xffffffffu, t1, 2));
        float mn0 = fmaxf(m0, t0), mn1 = fmaxf(m1, t1);
        float sc0 = __expf(m0 - mn0), sc1 = __expf(m1 - mn1);
        m0 = mn0; m1 = mn1;

        float ls0 = 0.f, ls1 = 0.f;
        #pragma unroll
        for (int nt = 0; nt < 8; nt++) {
            float p0 = __expf(sacc[nt][0] - mn0);
            float p1 = __expf(sacc[nt][1] - mn0);
            float p2 = __expf(sacc[nt][2] - mn1);
            float p3 = __expf(sacc[nt][3] - mn1);
            ls0 += p0 + p1;
            ls1 += p2 + p3;
            *(__half2*)&Ps[sr0 * HST + nt * 8 + 2 * q] = __floats2half2_rn(p0, p1);
            *(__half2*)&Ps[sr1 * HST + nt * 8 + 2 * q] = __floats2half2_rn(p2, p3);
        }
        ls0 += __shfl_xor_sync(0xffffffffu, ls0, 1);
        ls0 += __shfl_xor_sync(0xffffffffu, ls0, 2);
        ls1 += __shfl_xor_sync(0xffffffffu, ls1, 1);
        ls1 += __shfl_xor_sync(0xffffffffu, ls1, 2);
        l0 = l0 * sc0 + ls0;
        l1 = l1 * sc1 + ls1;
        if (q == 0) { scl[sr0] = sc0; scl[sr1] = sc1; }
        __syncthreads();

        #pragma unroll
        for (int nt = 0; nt < 8; nt++) {
            float s0 = scl[qb + nt * 8 + 2 * q];
            float s1 = scl[qb + nt * 8 + 2 * q + 1];
            oacc[nt][0] *= s0; oacc[nt][1] *= s1;
            oacc[nt][2] *= s0; oacc[nt][3] *= s1;
        }
        // ---- PV: O^T += V^T @ P^T ----
        #pragma unroll
        for (int ks = 0; ks < 4; ks++) {
            unsigned a0, a1, a2, a3;
            {
                const __half* src = &Vs[(ks * 16 + lm_kv) * HST + lm_d];
                unsigned saddr = (unsigned)__cvta_generic_to_shared(src);
                asm volatile(
                    "ldmatrix.sync.aligned.m8n8.x4.trans.shared.b16 "
                    "{%0,%1,%2,%3}, [%4];"
                    : "=r"(a0), "=r"(a1), "=r"(a2), "=r"(a3) : "r"(saddr));
            }
            const int kc = ks * 16 + 2 * q;
            #pragma unroll
            for (int nt = 0; nt < 8; nt++) {
                const __half* pr = &Ps[(qb + nt * 8 + g) * HST + kc];
                unsigned b0 = *(const unsigned*)pr;
                unsigned b1 = *(const unsigned*)(pr + 8);
                mma_f16(oacc[nt][0], oacc[nt][1], oacc[nt][2], oacc[nt][3],
                        a0, a1, a2, a3, b0, b1);
            }
        }
    }

    if (q == 0) { linv[sr0] = 1.f / l0; linv[sr1] = 1.f / l1; }
    __syncthreads();

    float* Osm = (float*)sm_h;   // 128 x OST floats
    #pragma unroll
    for (int nt = 0; nt < 8; nt++) {
        int qc = qb + nt * 8 + 2 * q;
        float i0 = linv[qc], i1 = linv[qc + 1];
        Osm[qc * OST + d0 + g]           = oacc[nt][0] * i0;
        Osm[(qc + 1) * OST + d0 + g]     = oacc[nt][1] * i1;
        Osm[qc * OST + d0 + g + 8]       = oacc[nt][2] * i0;
        Osm[(qc + 1) * OST + d0 + g + 8] = oacc[nt][3] * i1;
    }
    __syncthreads();

    #pragma unroll
    for (int i = 0; i < 8; i++) {
        int idx = tid + i * 256;
        int row = idx >> 4, c4 = (idx & 15) * 4;
        int r = q0 + row;
        if (r < NN) {
            float4 v = *(float4*)&Osm[row * OST + c4];
            *(float4*)(CTX + ((long long)(b * NN + r)) * DD + h * HD + c4) = v;
        }
    }
}

// ---------------------------------------------------------------------------
extern "C" void kernel_launch(void* const* d_in, const int* in_sizes, int n_in,
                              void* d_out, int out_size)
{
    const float* X    = (const float*)d_in[0];
    const float* sinp = (const float*)d_in[1];
    const float* cosp = (const float*)d_in[2];
    const float* Wq   = (const float*)d_in[3];
    const float* bq   = (const float*)d_in[4];
    const float* Wk   = (const float*)d_in[5];
    const float* bk   = (const float*)d_in[6];
    const float* Wv   = (const float*)d_in[7];
    const float* bv   = (const float*)d_in[8];
    const float* Wo   = (const float*)d_in[9];
    const float* bo   = (const float*)d_in[10];
    float* OUT = (float*)d_out;

    float *Qb, *Kb, *Vb, *CTX;
    cudaGetSymbolAddress((void**)&Qb,  g_Q);
    cudaGetSymbolAddress((void**)&Kb,  g_K);
    cudaGetSymbolAddress((void**)&Vb,  g_V);
    cudaGetSymbolAddress((void**)&CTX, g_CTX);

    cudaFuncSetAttribute(gemm_f16<0>,
                         cudaFuncAttributeMaxDynamicSharedMemorySize, GEMM_SMEM0);
    cudaFuncSetAttribute(gemm_f16<1>,
                         cudaFuncAttributeMaxDynamicSharedMemorySize, GEMM_SMEM1);
    cudaFuncSetAttribute(flash_attn_tc,
                         cudaFuncAttributeMaxDynamicSharedMemorySize, FA_SMEM);

    dim3 ggrid(DD / 128, (MM + 127) / 128);
    dim3 gblk(256);

    // Q/K projections with fused RoPE+transpose -> [B,H,N,HD]
    gemm_f16<1><<<ggrid, gblk, GEMM_SMEM1>>>(X, Wq, bq, Qb, MM, sinp, cosp);
    gemm_f16<1><<<ggrid, gblk, GEMM_SMEM1>>>(X, Wk, bk, Kb, MM, sinp, cosp);
    // V projection (stays in [B,N,H*HD]; attention reads it directly)
    gemm_f16<0><<<ggrid, gblk, GEMM_SMEM0>>>(X, Wv, bv, Vb, MM, sinp, cosp);

    // fp16 tensor-core attention
    dim3 agrid((NN + 127) / 128, HH, BB);   // (9,16,16)
    flash_attn_tc<<<agrid, 256, FA_SMEM>>>(Qb, Kb, Vb, CTX);

    // output projection straight into d_out
    gemm_f16<0><<<ggrid, gblk, GEMM_SMEM0>>>(CTX, Wo, bo, OUT, MM, sinp, cosp);
}

// round 14
// speedup vs baseline: 1.7436x; 1.1067x over previous
#include <cuda_runtime.h>
#include <cuda_fp16.h>
#include <cuda_bf16.h>

// Problem constants
#define BB   16
#define NN   1029
#define HH   16
#define HD   64
#define DD   1024
#define MM   (BB * NN)          // 16464
#define PREFIX 5                // N - NP
#define TOTAL  (MM * DD)        // 16859136

// Scratch (allocation-free rule: use __device__ globals)
__device__ float g_Q  [TOTAL];
__device__ float g_K  [TOTAL];
__device__ float g_V  [TOTAL];
__device__ float g_CTX[TOTAL];

__device__ __forceinline__ void mma_f16(
    float& c0, float& c1, float& c2, float& c3,
    unsigned a0, unsigned a1, unsigned a2, unsigned a3,
    unsigned b0, unsigned b1)
{
    asm volatile(
        "mma.sync.aligned.m16n8k16.row.col.f32.f16.f16.f32 "
        "{%0,%1,%2,%3}, {%4,%5,%6,%7}, {%8,%9}, {%0,%1,%2,%3};\n"
        : "+f"(c0), "+f"(c1), "+f"(c2), "+f"(c3)
        : "r"(a0), "r"(a1), "r"(a2), "r"(a3), "r"(b0), "r"(b1));
}

__device__ __forceinline__ unsigned packh2(float x, float y) {
    __half2 h = __floats2half2_rn(x, y);
    return *(unsigned*)&h;
}

// ---------------------------------------------------------------------------
// FP16 tensor-core GEMM NT: C[m,n] = sum_k A[m,k] * W[n,k] + bias[n]
// Double-buffered smem stages, one __syncthreads per chunk.
// MODE 0: plain row-major store.  MODE 1: fused RoPE + transpose store.
// ---------------------------------------------------------------------------
#define KH    40
#define STG   (128 * KH)
#define CPAD  132
#define GEMM_SMEM0 (4 * STG * 2)            // 40960 B
#define GEMM_SMEM1 (128 * CPAD * 4)         // 67584 B

template <int MODE>
__global__ __launch_bounds__(256) void gemm_f16(
    const float* __restrict__ A, const float* __restrict__ W,
    const float* __restrict__ bias, float* __restrict__ C, int M,
    const float* __restrict__ sinp, const float* __restrict__ cosp)
{
    extern __shared__ __align__(16) unsigned char smem_raw[];
    __half* Abuf = (__half*)smem_raw;       // 2 x 128 x KH
    __half* Wbuf = Abuf + 2 * STG;          // 2 x 128 x KH

    const int tid  = threadIdx.x;
    const int warp = tid >> 5;
    const int lane = tid & 31;
    const int g    = lane >> 2;
    const int q    = lane & 3;
    const int wm   = warp >> 2;
    const int wn   = warp & 3;
    const int row0 = blockIdx.y * 128;
    const int col0 = blockIdx.x * 128;

    float acc[4][4][4];
    #pragma unroll
    for (int mt = 0; mt < 4; mt++)
        #pragma unroll
        for (int nt = 0; nt < 4; nt++)
            #pragma unroll
            for (int i = 0; i < 4; i++) acc[mt][nt][i] = 0.f;

    int lrow[4], lk[4];
    #pragma unroll
    for (int j = 0; j < 4; j++) {
        int idx = tid + j * 256;
        lrow[j] = idx >> 3;
        lk[j]   = (idx & 7) * 4;
    }
    const bool arow_ok[4] = {
        row0 + lrow[0] < M, row0 + lrow[1] < M,
        row0 + lrow[2] < M, row0 + lrow[3] < M };
    const float* Ap[4];
    const float* Wp[4];
    #pragma unroll
    for (int j = 0; j < 4; j++) {
        Ap[j] = A + (long long)(row0 + lrow[j]) * DD + lk[j];
        Wp[j] = W + (long long)(col0 + lrow[j]) * DD + lk[j];
    }

    const float4 z4 = make_float4(0.f, 0.f, 0.f, 0.f);
    float4 pa[4], pw[4];

    #pragma unroll
    for (int j = 0; j < 4; j++) {
        pa[j] = arow_ok[j] ? *(const float4*)(Ap[j]) : z4;
        pw[j] = *(const float4*)(Wp[j]);
    }
    #pragma unroll
    for (int j = 0; j < 4; j++) {
        __half2* as = (__half2*)&Abuf[lrow[j] * KH + lk[j]];
        as[0] = __floats2half2_rn(pa[j].x, pa[j].y);
        as[1] = __floats2half2_rn(pa[j].z, pa[j].w);
        __half2* ws = (__half2*)&Wbuf[lrow[j] * KH + lk[j]];
        ws[0] = __floats2half2_rn(pw[j].x, pw[j].y);
        ws[1] = __floats2half2_rn(pw[j].z, pw[j].w);
    }
    __syncthreads();
    #pragma unroll
    for (int j = 0; j < 4; j++) {
        pa[j] = arow_ok[j] ? *(const float4*)(Ap[j] + 32) : z4;
        pw[j] = *(const float4*)(Wp[j] + 32);
    }

    for (int c = 0; c < DD / 32; c++) {
        const __half* Asm = Abuf + (c & 1) * STG;
        const __half* Wsm = Wbuf + (c & 1) * STG;

        #pragma unroll
        for (int ks = 0; ks < 2; ks++) {
            const int kc = ks * 16 + 2 * q;
            unsigned af[4][4], bf[4][2];
            #pragma unroll
            for (int mt = 0; mt < 4; mt++) {
                int row = wm * 64 + mt * 16 + g;
                af[mt][0] = *(const unsigned*)&Asm[row * KH + kc];
                af[mt][1] = *(const unsigned*)&Asm[(row + 8) * KH + kc];
                af[mt][2] = *(const unsigned*)&Asm[row * KH + kc + 8];
                af[mt][3] = *(const unsigned*)&Asm[(row + 8) * KH + kc + 8];
            }
            #pragma unroll
            for (int nt = 0; nt < 4; nt++) {
                int col = wn * 32 + nt * 8 + g;
                bf[nt][0] = *(const unsigned*)&Wsm[col * KH + kc];
                bf[nt][1] = *(const unsigned*)&Wsm[col * KH + kc + 8];
            }
            #pragma unroll
            for (int mt = 0; mt < 4; mt++)
                #pragma unroll
                for (int nt = 0; nt < 4; nt++)
                    mma_f16(acc[mt][nt][0], acc[mt][nt][1],
                            acc[mt][nt][2], acc[mt][nt][3],
                            af[mt][0], af[mt][1], af[mt][2], af[mt][3],
                            bf[nt][0], bf[nt][1]);
        }

        if (c + 1 < DD / 32) {
            __half* Ad = Abuf + ((c + 1) & 1) * STG;
            __half* Wd = Wbuf + ((c + 1) & 1) * STG;
            #pragma unroll
            for (int j = 0; j < 4; j++) {
                __half2* as = (__half2*)&Ad[lrow[j] * KH + lk[j]];
                as[0] = __floats2half2_rn(pa[j].x, pa[j].y);
                as[1] = __floats2half2_rn(pa[j].z, pa[j].w);
                __half2* ws = (__half2*)&Wd[lrow[j] * KH + lk[j]];
                ws[0] = __floats2half2_rn(pw[j].x, pw[j].y);
                ws[1] = __floats2half2_rn(pw[j].z, pw[j].w);
            }
        }
        if (c + 2 < DD / 32) {
            int kb = (c + 2) * 32;
            #pragma unroll
            for (int j = 0; j < 4; j++) {
                pa[j] = arow_ok[j] ? *(const float4*)(Ap[j] + kb) : z4;
                pw[j] = *(const float4*)(Wp[j] + kb);
            }
        }
        __syncthreads();
    }

    if (MODE == 0) {
        #pragma unroll
        for (int mt = 0; mt < 4; mt++) {
            int r0 = row0 + wm * 64 + mt * 16 + g;
            int r1 = r0 + 8;
            #pragma unroll
            for (int nt = 0; nt < 4; nt++) {
                int c = col0 + wn * 32 + nt * 8 + 2 * q;
                float bx = bias[c], by = bias[c + 1];
                if (r0 < M) {
                    float2 v = make_float2(acc[mt][nt][0] + bx, acc[mt][nt][1] + by);
                    *(float2*)(C + (long long)r0 * DD + c) = v;
                }
                if (r1 < M) {
                    float2 v = make_float2(acc[mt][nt][2] + bx, acc[mt][nt][3] + by);
                    *(float2*)(C + (long long)r1 * DD + c) = v;
                }
            }
        }
    } else {
        float* Cs = (float*)smem_raw;   // 128 x CPAD
        #pragma unroll
        for (int mt = 0; mt < 4; mt++) {
            int lr0 = wm * 64 + mt * 16 + g;
            int lr1 = lr0 + 8;
            #pragma unroll
            for (int nt = 0; nt < 4; nt++) {
                int lc = wn * 32 + nt * 8 + 2 * q;
                float bx = bias[col0 + lc], by = bias[col0 + lc + 1];
                *(float2*)&Cs[lr0 * CPAD + lc] =
                    make_float2(acc[mt][nt][0] + bx, acc[mt][nt][1] + by);
                *(float2*)&Cs[lr1 * CPAD + lc] =
                    make_float2(acc[mt][nt][2] + bx, acc[mt][nt][3] + by);
            }
        }
        __syncthreads();

        #pragma unroll
        for (int i = 0; i < 16; i++) {
            int idx = tid + i * 256;
            int row = idx >> 5;
            int c4  = (idx & 31) * 4;
            int R = row0 + row;
            if (R >= M) continue;
            int b = R / NN;
            int t = R - b * NN;
            int gcol = col0 + c4;
            int h = gcol >> 6;
            int d = gcol & 63;

            float4 x = *(float4*)&Cs[row * CPAD + c4];
            float4 v = x;
            if (t >= PREFIX) {
                int pos = t - PREFIX;
                float4 cc = *(const float4*)(cosp + pos * HD + d);
                float4 ss = *(const float4*)(sinp + pos * HD + d);
                float4 xo = *(float4*)&Cs[row * CPAD + (c4 ^ 32)];
                if (d < 32) { xo.x = -xo.x; xo.y = -xo.y; xo.z = -xo.z; xo.w = -xo.w; }
                v.x = x.x * cc.x + xo.x * ss.x;
                v.y = x.y * cc.y + xo.y * ss.y;
                v.z = x.z * cc.z + xo.z * ss.z;
                v.w = x.w * cc.w + xo.w * ss.w;
            }
            *(float4*)(C + (((long long)(b * HH + h)) * NN + t) * HD + d) = v;
        }
    }
}

// ---------------------------------------------------------------------------
// FP16 flash attention v3: NO P round-trip.
// Each warp owns 16 q rows end-to-end: S accumulator (16q x 64kv) repacks
// in-register into PV A-fragments; PV computes O[q][d] directly.
// B-operand (V^T frags) via ldmatrix.x4.trans from row-major V tile.
// Q fragments hoisted to registers (tile-invariant).
// Smem: Qs + Ks + Vs only = 36864 B; 2 CTAs/SM.
// ---------------------------------------------------------------------------
#define HST 72
#define FA_SMEM ((128 + 64 + 64) * HST * 2)   // 36864 B

__global__ __launch_bounds__(256, 2) void flash_attn_tc(
    const float* __restrict__ Q, const float* __restrict__ K,
    const float* __restrict__ Vy, float* __restrict__ CTX)
{
    extern __shared__ __half sm_h[];
    __half* Qs = sm_h;                  // 128 x HST
    __half* Ks = Qs + 128 * HST;        // 64 x HST (kv x d)
    __half* Vs = Ks + 64 * HST;         // 64 x HST (kv x d)

    const int q0 = blockIdx.x * 128;
    const int h  = blockIdx.y;
    const int b  = blockIdx.z;
    const long long baseQ = ((long long)(b * HH + h)) * NN * HD;
    const int tid  = threadIdx.x;
    const int warp = tid >> 5;
    const int lane = tid & 31;
    const int g    = lane >> 2;
    const int q    = lane & 3;
    const int sr0  = warp * 16 + g;     // this warp's q rows
    const int sr1  = sr0 + 8;

    // ldmatrix source for V^T frags: row = kc + (lane&15), col = ntp*16 + (lane>>4)*8
    const int lm_r = lane & 15;
    const int lm_c = (lane >> 4) * 8;

    // load Q tile (scaled by HD^-0.5)
    #pragma unroll
    for (int i = 0; i < 8; i++) {
        int idx = tid + i * 256;
        int row = idx >> 4, c4 = (idx & 15) * 4;
        int r = q0 + row;
        float4 v = (r < NN) ? *(const float4*)(Q + baseQ + (long long)r * HD + c4)
                            : make_float4(0.f, 0.f, 0.f, 0.f);
        __half2* p = (__half2*)&Qs[row * HST + c4];
        p[0] = __floats2half2_rn(v.x * 0.125f, v.y * 0.125f);
        p[1] = __floats2half2_rn(v.z * 0.125f, v.w * 0.125f);
    }
    __syncthreads();

    // hoist Q fragments into registers (constant across kv tiles)
    unsigned qa[4][4];
    #pragma unroll
    for (int ks = 0; ks < 4; ks++) {
        const int kc = ks * 16 + 2 * q;
        qa[ks][0] = *(const unsigned*)&Qs[sr0 * HST + kc];
        qa[ks][1] = *(const unsigned*)&Qs[sr1 * HST + kc];
        qa[ks][2] = *(const unsigned*)&Qs[sr0 * HST + kc + 8];
        qa[ks][3] = *(const unsigned*)&Qs[sr1 * HST + kc + 8];
    }

    float m0 = -1e30f, m1 = -1e30f, l0 = 0.f, l1 = 0.f;
    float oacc[8][4];
    #pragma unroll
    for (int nt = 0; nt < 8; nt++)
        #pragma unroll
        for (int i = 0; i < 4; i++) oacc[nt][i] = 0.f;

    for (int k0 = 0; k0 < NN; k0 += 64) {
        __syncthreads();    // previous tile's S/PV reads complete
        #pragma unroll
        for (int i = 0; i < 4; i++) {
            int idx = tid + i * 256;
            int j = idx >> 4, c4 = (idx & 15) * 4;
            int kv = k0 + j;
            float4 kvec, vvec;
            if (kv < NN) {
                kvec = *(const float4*)(K + baseQ + (long long)kv * HD + c4);
                vvec = *(const float4*)(Vy + ((long long)(b * NN + kv)) * DD + h * HD + c4);
            } else {
                kvec = make_float4(0.f, 0.f, 0.f, 0.f);
                vvec = kvec;
            }
            __half2* pk = (__half2*)&Ks[j * HST + c4];
            pk[0] = __floats2half2_rn(kvec.x, kvec.y);
            pk[1] = __floats2half2_rn(kvec.z, kvec.w);
            __half2* pv = (__half2*)&Vs[j * HST + c4];
            pv[0] = __floats2half2_rn(vvec.x, vvec.y);
            pv[1] = __floats2half2_rn(vvec.z, vvec.w);
        }
        __syncthreads();

        // ---- S = Q @ K^T (16q x 64kv per warp) ----
        float sacc[8][4];
        #pragma unroll
        for (int nt = 0; nt < 8; nt++)
            #pragma unroll
            for (int i = 0; i < 4; i++) sacc[nt][i] = 0.f;

        #pragma unroll
        for (int ks = 0; ks < 4; ks++) {
            const int kc = ks * 16 + 2 * q;
            #pragma unroll
            for (int nt = 0; nt < 8; nt++) {
                const __half* kr = &Ks[(nt * 8 + g) * HST + kc];
                unsigned b0 = *(const unsigned*)kr;
                unsigned b1 = *(const unsigned*)(kr + 8);
                mma_f16(sacc[nt][0], sacc[nt][1], sacc[nt][2], sacc[nt][3],
                        qa[ks][0], qa[ks][1], qa[ks][2], qa[ks][3], b0, b1);
            }
        }

        if (k0 + 64 > NN) {
            #pragma unroll
            for (int nt = 0; nt < 8; nt++) {
                int c = k0 + nt * 8 + 2 * q;
                if (c >= NN)     { sacc[nt][0] = -1e30f; sacc[nt][2] = -1e30f; }
                if (c + 1 >= NN) { sacc[nt][1] = -1e30f; sacc[nt][3] = -1e30f; }
            }
        }

        // ---- online softmax (quad-wide row reductions) ----
        float t0 = -1e30f, t1 = -1e30f;
        #pragma unroll
        for (int nt = 0; nt < 8; nt++) {
            t0 = fmaxf(t0, fmaxf(sacc[nt][0], sacc[nt][1]));
            t1 = fmaxf(t1, fmaxf(sacc[nt][2], sacc[nt][3]));
        }
        t0 = fmaxf(t0, __shfl_xor_sync(0xffffffffu, t0, 1));
        t0 = fmaxf(t0, __shfl_xor_sync(0xffffffffu, t0, 2));
        t1 = fmaxf(t1, __shfl_xor_sync(0xffffffffu, t1, 1));
        t1 = fmaxf(t1, __shfl_xor_sync(0xffffffffu, t1, 2));
        float mn0 = fmaxf(m0, t0), mn1 = fmaxf(m1, t1);
        float sc0 = __expf(m0 - mn0), sc1 = __expf(m1 - mn1);
        m0 = mn0; m1 = mn1;

        // p = exp(s - m): pack straight into PV A-fragments (registers only)
        unsigned pa[4][4];
        float ls0 = 0.f, ls1 = 0.f;
        #pragma unroll
        for (int nt = 0; nt < 8; nt++) {
            float p0 = __expf(sacc[nt][0] - mn0);
            float p1 = __expf(sacc[nt][1] - mn0);
            float p2 = __expf(sacc[nt][2] - mn1);
            float p3 = __expf(sacc[nt][3] - mn1);
            ls0 += p0 + p1;
            ls1 += p2 + p3;
            if ((nt & 1) == 0) {
                pa[nt >> 1][0] = packh2(p0, p1);
                pa[nt >> 1][1] = packh2(p2, p3);
            } else {
                pa[nt >> 1][2] = packh2(p0, p1);
                pa[nt >> 1][3] = packh2(p2, p3);
            }
        }
        ls0 += __shfl_xor_sync(0xffffffffu, ls0, 1);
        ls0 += __shfl_xor_sync(0xffffffffu, ls0, 2);
        ls1 += __shfl_xor_sync(0xffffffffu, ls1, 1);
        ls1 += __shfl_xor_sync(0xffffffffu, ls1, 2);
        l0 = l0 * sc0 + ls0;
        l1 = l1 * sc1 + ls1;

        // rescale O accumulators (per-row factors known in-register)
        #pragma unroll
        for (int nt = 0; nt < 8; nt++) {
            oacc[nt][0] *= sc0; oacc[nt][1] *= sc0;
            oacc[nt][2] *= sc1; oacc[nt][3] *= sc1;
        }

        // ---- PV: O[16q x 64d] += P @ V  (A from regs, B via ldmatrix.trans) ----
        #pragma unroll
        for (int ks = 0; ks < 4; ks++) {
            const int kc = ks * 16;
            #pragma unroll
            for (int ntp = 0; ntp < 4; ntp++) {
                unsigned v0, v1, v2, v3;
                const __half* src = &Vs[(kc + lm_r) * HST + ntp * 16 + lm_c];
                unsigned saddr = (unsigned)__cvta_generic_to_shared(src);
                asm volatile(
                    "ldmatrix.sync.aligned.m8n8.x4.trans.shared.b16 "
                    "{%0,%1,%2,%3}, [%4];"
                    : "=r"(v0), "=r"(v1), "=r"(v2), "=r"(v3) : "r"(saddr));
                mma_f16(oacc[2*ntp][0], oacc[2*ntp][1], oacc[2*ntp][2], oacc[2*ntp][3],
                        pa[ks][0], pa[ks][1], pa[ks][2], pa[ks][3], v0, v1);
                mma_f16(oacc[2*ntp+1][0], oacc[2*ntp+1][1], oacc[2*ntp+1][2], oacc[2*ntp+1][3],
                        pa[ks][0], pa[ks][1], pa[ks][2], pa[ks][3], v2, v3);
            }
        }
    }

    // ---- epilogue: normalize and store own rows directly ----
    float inv0 = 1.f / l0, inv1 = 1.f / l1;
    int r0 = q0 + sr0;
    int r1 = q0 + sr1;
    #pragma unroll
    for (int nt = 0; nt < 8; nt++) {
        int col = h * HD + nt * 8 + 2 * q;
        if (r0 < NN) {
            float2 v = make_float2(oacc[nt][0] * inv0, oacc[nt][1] * inv0);
            *(float2*)(CTX + ((long long)(b * NN + r0)) * DD + col) = v;
        }
        if (r1 < NN) {
            float2 v = make_float2(oacc[nt][2] * inv1, oacc[nt][3] * inv1);
            *(float2*)(CTX + ((long long)(b * NN + r1)) * DD + col) = v;
        }
    }
}

// ---------------------------------------------------------------------------
extern "C" void kernel_launch(void* const* d_in, const int* in_sizes, int n_in,
                              void* d_out, int out_size)
{
    const float* X    = (const float*)d_in[0];
    const float* sinp = (const float*)d_in[1];
    const float* cosp = (const float*)d_in[2];
    const float* Wq   = (const float*)d_in[3];
    const float* bq   = (const float*)d_in[4];
    const float* Wk   = (const float*)d_in[5];
    const float* bk   = (const float*)d_in[6];
    const float* Wv   = (const float*)d_in[7];
    const float* bv   = (const float*)d_in[8];
    const float* Wo   = (const float*)d_in[9];
    const float* bo   = (const float*)d_in[10];
    float* OUT = (float*)d_out;

    float *Qb, *Kb, *Vb, *CTX;
    cudaGetSymbolAddress((void**)&Qb,  g_Q);
    cudaGetSymbolAddress((void**)&Kb,  g_K);
    cudaGetSymbolAddress((void**)&Vb,  g_V);
    cudaGetSymbolAddress((void**)&CTX, g_CTX);

    cudaFuncSetAttribute(gemm_f16<0>,
                         cudaFuncAttributeMaxDynamicSharedMemorySize, GEMM_SMEM0);
    cudaFuncSetAttribute(gemm_f16<1>,
                         cudaFuncAttributeMaxDynamicSharedMemorySize, GEMM_SMEM1);
    cudaFuncSetAttribute(flash_attn_tc,
                         cudaFuncAttributeMaxDynamicSharedMemorySize, FA_SMEM);

    dim3 ggrid(DD / 128, (MM + 127) / 128);
    dim3 gblk(256);

    // Q/K projections with fused RoPE+transpose -> [B,H,N,HD]
    gemm_f16<1><<<ggrid, gblk, GEMM_SMEM1>>>(X, Wq, bq, Qb, MM, sinp, cosp);
    gemm_f16<1><<<ggrid, gblk, GEMM_SMEM1>>>(X, Wk, bk, Kb, MM, sinp, cosp);
    // V projection (stays in [B,N,H*HD]; attention reads it directly)
    gemm_f16<0><<<ggrid, gblk, GEMM_SMEM0>>>(X, Wv, bv, Vb, MM, sinp, cosp);

    // fp16 tensor-core attention
    dim3 agrid((NN + 127) / 128, HH, BB);   // (9,16,16)
    flash_attn_tc<<<agrid, 256, FA_SMEM>>>(Qb, Kb, Vb, CTX);

    // output projection straight into d_out
    gemm_f16<0><<<ggrid, gblk, GEMM_SMEM0>>>(CTX, Wo, bo, OUT, MM, sinp, cosp);
}

// round 15
// speedup vs baseline: 1.8370x; 1.0536x over previous
#include <cuda_runtime.h>
#include <cuda_fp16.h>
#include <cuda_bf16.h>

// Problem constants
#define BB   16
#define NN   1029
#define HH   16
#define HD   64
#define DD   1024
#define MM   (BB * NN)          // 16464
#define PREFIX 5                // N - NP
#define TOTAL  (MM * DD)        // 16859136

// Scratch (allocation-free rule: use __device__ globals)
__device__ float g_Q  [TOTAL];
__device__ float g_K  [TOTAL];
__device__ float g_V  [TOTAL];
__device__ float g_CTX[TOTAL];

__device__ __forceinline__ void mma_f16(
    float& c0, float& c1, float& c2, float& c3,
    unsigned a0, unsigned a1, unsigned a2, unsigned a3,
    unsigned b0, unsigned b1)
{
    asm volatile(
        "mma.sync.aligned.m16n8k16.row.col.f32.f16.f16.f32 "
        "{%0,%1,%2,%3}, {%4,%5,%6,%7}, {%8,%9}, {%0,%1,%2,%3};\n"
        : "+f"(c0), "+f"(c1), "+f"(c2), "+f"(c3)
        : "r"(a0), "r"(a1), "r"(a2), "r"(a3), "r"(b0), "r"(b1));
}

__device__ __forceinline__ void ldsm_x4(
    unsigned& r0, unsigned& r1, unsigned& r2, unsigned& r3, const __half* src)
{
    unsigned saddr = (unsigned)__cvta_generic_to_shared(src);
    asm volatile(
        "ldmatrix.sync.aligned.m8n8.x4.shared.b16 {%0,%1,%2,%3}, [%4];"
        : "=r"(r0), "=r"(r1), "=r"(r2), "=r"(r3) : "r"(saddr));
}

__device__ __forceinline__ unsigned packh2(float x, float y) {
    __half2 h = __floats2half2_rn(x, y);
    return *(unsigned*)&h;
}

// ---------------------------------------------------------------------------
// FP16 tensor-core GEMM NT: C[m,n] = sum_k A[m,k] * W[n,k] + bias[n]
// Double-buffered smem stages; fragments via ldmatrix.x4 (conflict-free:
// row stride 80B = 5 x 16B units, coprime with 8).
// MODE 0: plain row-major store.  MODE 1: fused RoPE + transpose store.
// ---------------------------------------------------------------------------
#define KH    40
#define STG   (128 * KH)
#define CPAD  132
#define GEMM_SMEM0 (4 * STG * 2)            // 40960 B
#define GEMM_SMEM1 (128 * CPAD * 4)         // 67584 B

template <int MODE>
__global__ __launch_bounds__(256) void gemm_f16(
    const float* __restrict__ A, const float* __restrict__ W,
    const float* __restrict__ bias, float* __restrict__ C, int M,
    const float* __restrict__ sinp, const float* __restrict__ cosp)
{
    extern __shared__ __align__(16) unsigned char smem_raw[];
    __half* Abuf = (__half*)smem_raw;       // 2 x 128 x KH
    __half* Wbuf = Abuf + 2 * STG;          // 2 x 128 x KH

    const int tid  = threadIdx.x;
    const int warp = tid >> 5;
    const int lane = tid & 31;
    const int g    = lane >> 2;
    const int q    = lane & 3;
    const int wm   = warp >> 2;
    const int wn   = warp & 3;
    const int row0 = blockIdx.y * 128;
    const int col0 = blockIdx.x * 128;

    // ldmatrix lane-address components
    const int lmA_r = (lane & 7) + ((lane >> 3) & 1) * 8;   // m row offset
    const int lmA_k = ((lane >> 4) & 1) * 8;                // k offset
    const int lmB_r = (lane & 7) + ((lane >> 4) & 1) * 8;   // n row offset
    const int lmB_k = ((lane >> 3) & 1) * 8;                // k offset

    float acc[4][4][4];
    #pragma unroll
    for (int mt = 0; mt < 4; mt++)
        #pragma unroll
        for (int nt = 0; nt < 4; nt++)
            #pragma unroll
            for (int i = 0; i < 4; i++) acc[mt][nt][i] = 0.f;

    int lrow[4], lk[4];
    #pragma unroll
    for (int j = 0; j < 4; j++) {
        int idx = tid + j * 256;
        lrow[j] = idx >> 3;
        lk[j]   = (idx & 7) * 4;
    }
    const bool arow_ok[4] = {
        row0 + lrow[0] < M, row0 + lrow[1] < M,
        row0 + lrow[2] < M, row0 + lrow[3] < M };
    const float* Ap[4];
    const float* Wp[4];
    #pragma unroll
    for (int j = 0; j < 4; j++) {
        Ap[j] = A + (long long)(row0 + lrow[j]) * DD + lk[j];
        Wp[j] = W + (long long)(col0 + lrow[j]) * DD + lk[j];
    }

    const float4 z4 = make_float4(0.f, 0.f, 0.f, 0.f);
    float4 pa[4], pw[4];

    #pragma unroll
    for (int j = 0; j < 4; j++) {
        pa[j] = arow_ok[j] ? *(const float4*)(Ap[j]) : z4;
        pw[j] = *(const float4*)(Wp[j]);
    }
    #pragma unroll
    for (int j = 0; j < 4; j++) {
        __half2* as = (__half2*)&Abuf[lrow[j] * KH + lk[j]];
        as[0] = __floats2half2_rn(pa[j].x, pa[j].y);
        as[1] = __floats2half2_rn(pa[j].z, pa[j].w);
        __half2* ws = (__half2*)&Wbuf[lrow[j] * KH + lk[j]];
        ws[0] = __floats2half2_rn(pw[j].x, pw[j].y);
        ws[1] = __floats2half2_rn(pw[j].z, pw[j].w);
    }
    __syncthreads();
    #pragma unroll
    for (int j = 0; j < 4; j++) {
        pa[j] = arow_ok[j] ? *(const float4*)(Ap[j] + 32) : z4;
        pw[j] = *(const float4*)(Wp[j] + 32);
    }

    for (int c = 0; c < DD / 32; c++) {
        const __half* Asm = Abuf + (c & 1) * STG;
        const __half* Wsm = Wbuf + (c & 1) * STG;

        #pragma unroll
        for (int ks = 0; ks < 2; ks++) {
            const int kc = ks * 16;
            unsigned af[4][4], bf[4][2];
            #pragma unroll
            for (int mt = 0; mt < 4; mt++) {
                ldsm_x4(af[mt][0], af[mt][1], af[mt][2], af[mt][3],
                        &Asm[(wm * 64 + mt * 16 + lmA_r) * KH + kc + lmA_k]);
            }
            #pragma unroll
            for (int p = 0; p < 2; p++) {
                ldsm_x4(bf[2*p][0], bf[2*p][1], bf[2*p+1][0], bf[2*p+1][1],
                        &Wsm[(wn * 32 + p * 16 + lmB_r) * KH + kc + lmB_k]);
            }
            #pragma unroll
            for (int mt = 0; mt < 4; mt++)
                #pragma unroll
                for (int nt = 0; nt < 4; nt++)
                    mma_f16(acc[mt][nt][0], acc[mt][nt][1],
                            acc[mt][nt][2], acc[mt][nt][3],
                            af[mt][0], af[mt][1], af[mt][2], af[mt][3],
                            bf[nt][0], bf[nt][1]);
        }

        if (c + 1 < DD / 32) {
            __half* Ad = Abuf + ((c + 1) & 1) * STG;
            __half* Wd = Wbuf + ((c + 1) & 1) * STG;
            #pragma unroll
            for (int j = 0; j < 4; j++) {
                __half2* as = (__half2*)&Ad[lrow[j] * KH + lk[j]];
                as[0] = __floats2half2_rn(pa[j].x, pa[j].y);
                as[1] = __floats2half2_rn(pa[j].z, pa[j].w);
                __half2* ws = (__half2*)&Wd[lrow[j] * KH + lk[j]];
                ws[0] = __floats2half2_rn(pw[j].x, pw[j].y);
                ws[1] = __floats2half2_rn(pw[j].z, pw[j].w);
            }
        }
        if (c + 2 < DD / 32) {
            int kb = (c + 2) * 32;
            #pragma unroll
            for (int j = 0; j < 4; j++) {
                pa[j] = arow_ok[j] ? *(const float4*)(Ap[j] + kb) : z4;
                pw[j] = *(const float4*)(Wp[j] + kb);
            }
        }
        __syncthreads();
    }

    if (MODE == 0) {
        #pragma unroll
        for (int mt = 0; mt < 4; mt++) {
            int r0 = row0 + wm * 64 + mt * 16 + g;
            int r1 = r0 + 8;
            #pragma unroll
            for (int nt = 0; nt < 4; nt++) {
                int c = col0 + wn * 32 + nt * 8 + 2 * q;
                float bx = bias[c], by = bias[c + 1];
                if (r0 < M) {
                    float2 v = make_float2(acc[mt][nt][0] + bx, acc[mt][nt][1] + by);
                    *(float2*)(C + (long long)r0 * DD + c) = v;
                }
                if (r1 < M) {
                    float2 v = make_float2(acc[mt][nt][2] + bx, acc[mt][nt][3] + by);
                    *(float2*)(C + (long long)r1 * DD + c) = v;
                }
            }
        }
    } else {
        float* Cs = (float*)smem_raw;   // 128 x CPAD
        #pragma unroll
        for (int mt = 0; mt < 4; mt++) {
            int lr0 = wm * 64 + mt * 16 + g;
            int lr1 = lr0 + 8;
            #pragma unroll
            for (int nt = 0; nt < 4; nt++) {
                int lc = wn * 32 + nt * 8 + 2 * q;
                float bx = bias[col0 + lc], by = bias[col0 + lc + 1];
                *(float2*)&Cs[lr0 * CPAD + lc] =
                    make_float2(acc[mt][nt][0] + bx, acc[mt][nt][1] + by);
                *(float2*)&Cs[lr1 * CPAD + lc] =
                    make_float2(acc[mt][nt][2] + bx, acc[mt][nt][3] + by);
            }
        }
        __syncthreads();

        #pragma unroll
        for (int i = 0; i < 16; i++) {
            int idx = tid + i * 256;
            int row = idx >> 5;
            int c4  = (idx & 31) * 4;
            int R = row0 + row;
            if (R >= M) continue;
            int b = R / NN;
            int t = R - b * NN;
            int gcol = col0 + c4;
            int h = gcol >> 6;
            int d = gcol & 63;

            float4 x = *(float4*)&Cs[row * CPAD + c4];
            float4 v = x;
            if (t >= PREFIX) {
                int pos = t - PREFIX;
                float4 cc = *(const float4*)(cosp + pos * HD + d);
                float4 ss = *(const float4*)(sinp + pos * HD + d);
                float4 xo = *(float4*)&Cs[row * CPAD + (c4 ^ 32)];
                if (d < 32) { xo.x = -xo.x; xo.y = -xo.y; xo.z = -xo.z; xo.w = -xo.w; }
                v.x = x.x * cc.x + xo.x * ss.x;
                v.y = x.y * cc.y + xo.y * ss.y;
                v.z = x.z * cc.z + xo.z * ss.z;
                v.w = x.w * cc.w + xo.w * ss.w;
            }
            *(float4*)(C + (((long long)(b * HH + h)) * NN + t) * HD + d) = v;
        }
    }
}

// ---------------------------------------------------------------------------
// FP16 flash attention v3 + ldmatrix K-fragments.
// Each warp owns 16 q rows end-to-end; P stays in registers.
// Smem: Qs + Ks + Vs = 36864 B; 2 CTAs/SM.
// ---------------------------------------------------------------------------
#define HST 72
#define FA_SMEM ((128 + 64 + 64) * HST * 2)   // 36864 B

__global__ __launch_bounds__(256, 2) void flash_attn_tc(
    const float* __restrict__ Q, const float* __restrict__ K,
    const float* __restrict__ Vy, float* __restrict__ CTX)
{
    extern __shared__ __half sm_h[];
    __half* Qs = sm_h;                  // 128 x HST
    __half* Ks = Qs + 128 * HST;        // 64 x HST (kv x d)
    __half* Vs = Ks + 64 * HST;         // 64 x HST (kv x d)

    const int q0 = blockIdx.x * 128;
    const int h  = blockIdx.y;
    const int b  = blockIdx.z;
    const long long baseQ = ((long long)(b * HH + h)) * NN * HD;
    const int tid  = threadIdx.x;
    const int warp = tid >> 5;
    const int lane = tid & 31;
    const int g    = lane >> 2;
    const int q    = lane & 3;
    const int sr0  = warp * 16 + g;     // this warp's q rows
    const int sr1  = sr0 + 8;

    // ldmatrix lane-address components
    const int lmB_r = (lane & 7) + ((lane >> 4) & 1) * 8;   // kv row (B-frag)
    const int lmB_k = ((lane >> 3) & 1) * 8;                // d/k offset
    const int lm_r  = lane & 15;                            // V trans rows
    const int lm_c  = (lane >> 4) * 8;                      // V trans col

    // load Q tile (scaled by HD^-0.5)
    #pragma unroll
    for (int i = 0; i < 8; i++) {
        int idx = tid + i * 256;
        int row = idx >> 4, c4 = (idx & 15) * 4;
        int r = q0 + row;
        float4 v = (r < NN) ? *(const float4*)(Q + baseQ + (long long)r * HD + c4)
                            : make_float4(0.f, 0.f, 0.f, 0.f);
        __half2* p = (__half2*)&Qs[row * HST + c4];
        p[0] = __floats2half2_rn(v.x * 0.125f, v.y * 0.125f);
        p[1] = __floats2half2_rn(v.z * 0.125f, v.w * 0.125f);
    }
    __syncthreads();

    // hoist Q fragments into registers (tile-invariant), via ldmatrix
    unsigned qa[4][4];
    {
        const int lmA_r = (lane & 7) + ((lane >> 3) & 1) * 8;
        const int lmA_k = ((lane >> 4) & 1) * 8;
        #pragma unroll
        for (int ks = 0; ks < 4; ks++)
            ldsm_x4(qa[ks][0], qa[ks][1], qa[ks][2], qa[ks][3],
                    &Qs[(warp * 16 + lmA_r) * HST + ks * 16 + lmA_k]);
    }

    float m0 = -1e30f, m1 = -1e30f, l0 = 0.f, l1 = 0.f;
    float oacc[8][4];
    #pragma unroll
    for (int nt = 0; nt < 8; nt++)
        #pragma unroll
        for (int i = 0; i < 4; i++) oacc[nt][i] = 0.f;

    for (int k0 = 0; k0 < NN; k0 += 64) {
        __syncthreads();
        #pragma unroll
        for (int i = 0; i < 4; i++) {
            int idx = tid + i * 256;
            int j = idx >> 4, c4 = (idx & 15) * 4;
            int kv = k0 + j;
            float4 kvec, vvec;
            if (kv < NN) {
                kvec = *(const float4*)(K + baseQ + (long long)kv * HD + c4);
                vvec = *(const float4*)(Vy + ((long long)(b * NN + kv)) * DD + h * HD + c4);
            } else {
                kvec = make_float4(0.f, 0.f, 0.f, 0.f);
                vvec = kvec;
            }
            __half2* pk = (__half2*)&Ks[j * HST + c4];
            pk[0] = __floats2half2_rn(kvec.x, kvec.y);
            pk[1] = __floats2half2_rn(kvec.z, kvec.w);
            __half2* pv = (__half2*)&Vs[j * HST + c4];
            pv[0] = __floats2half2_rn(vvec.x, vvec.y);
            pv[1] = __floats2half2_rn(vvec.z, vvec.w);
        }
        __syncthreads();

        // ---- S = Q @ K^T (16q x 64kv per warp), K-frags via ldmatrix ----
        float sacc[8][4];
        #pragma unroll
        for (int nt = 0; nt < 8; nt++)
            #pragma unroll
            for (int i = 0; i < 4; i++) sacc[nt][i] = 0.f;

        #pragma unroll
        for (int ks = 0; ks < 4; ks++) {
            const int kc = ks * 16;
            #pragma unroll
            for (int p = 0; p < 4; p++) {
                unsigned b0, b1, b2, b3;
                ldsm_x4(b0, b1, b2, b3,
                        &Ks[(p * 16 + lmB_r) * HST + kc + lmB_k]);
                mma_f16(sacc[2*p][0], sacc[2*p][1], sacc[2*p][2], sacc[2*p][3],
                        qa[ks][0], qa[ks][1], qa[ks][2], qa[ks][3], b0, b1);
                mma_f16(sacc[2*p+1][0], sacc[2*p+1][1], sacc[2*p+1][2], sacc[2*p+1][3],
                        qa[ks][0], qa[ks][1], qa[ks][2], qa[ks][3], b2, b3);
            }
        }

        if (k0 + 64 > NN) {
            #pragma unroll
            for (int nt = 0; nt < 8; nt++) {
                int c = k0 + nt * 8 + 2 * q;
                if (c >= NN)     { sacc[nt][0] = -1e30f; sacc[nt][2] = -1e30f; }
                if (c + 1 >= NN) { sacc[nt][1] = -1e30f; sacc[nt][3] = -1e30f; }
            }
        }

        // ---- online softmax (quad-wide row reductions) ----
        float t0 = -1e30f, t1 = -1e30f;
        #pragma unroll
        for (int nt = 0; nt < 8; nt++) {
            t0 = fmaxf(t0, fmaxf(sacc[nt][0], sacc[nt][1]));
            t1 = fmaxf(t1, fmaxf(sacc[nt][2], sacc[nt][3]));
        }
        t0 = fmaxf(t0, __shfl_xor_sync(0xffffffffu, t0, 1));
        t0 = fmaxf(t0, __shfl_xor_sync(0xffffffffu, t0, 2));
        t1 = fmaxf(t1, __shfl_xor_sync(0xffffffffu, t1, 1));
        t1 = fmaxf(t1, __shfl_xor_sync(0xffffffffu, t1, 2));
        float mn0 = fmaxf(m0, t0), mn1 = fmaxf(m1, t1);
        float sc0 = __expf(m0 - mn0), sc1 = __expf(m1 - mn1);
        m0 = mn0; m1 = mn1;

        // p = exp(s - m): pack straight into PV A-fragments (registers only)
        unsigned pa[4][4];
        float ls0 = 0.f, ls1 = 0.f;
        #pragma unroll
        for (int nt = 0; nt < 8; nt++) {
            float p0 = __expf(sacc[nt][0] - mn0);
            float p1 = __expf(sacc[nt][1] - mn0);
            float p2 = __expf(sacc[nt][2] - mn1);
            float p3 = __expf(sacc[nt][3] - mn1);
            ls0 += p0 + p1;
            ls1 += p2 + p3;
            if ((nt & 1) == 0) {
                pa[nt >> 1][0] = packh2(p0, p1);
                pa[nt >> 1][1] = packh2(p2, p3);
            } else {
                pa[nt >> 1][2] = packh2(p0, p1);
                pa[nt >> 1][3] = packh2(p2, p3);
            }
        }
        ls0 += __shfl_xor_sync(0xffffffffu, ls0, 1);
        ls0 += __shfl_xor_sync(0xffffffffu, ls0, 2);
        ls1 += __shfl_xor_sync(0xffffffffu, ls1, 1);
        ls1 += __shfl_xor_sync(0xffffffffu, ls1, 2);
        l0 = l0 * sc0 + ls0;
        l1 = l1 * sc1 + ls1;

        // rescale O accumulators
        #pragma unroll
        for (int nt = 0; nt < 8; nt++) {
            oacc[nt][0] *= sc0; oacc[nt][1] *= sc0;
            oacc[nt][2] *= sc1; oacc[nt][3] *= sc1;
        }

        // ---- PV: O[16q x 64d] += P @ V (A regs, B via ldmatrix.trans) ----
        #pragma unroll
        for (int ks = 0; ks < 4; ks++) {
            const int kc = ks * 16;
            #pragma unroll
            for (int ntp = 0; ntp < 4; ntp++) {
                unsigned v0, v1, v2, v3;
                const __half* src = &Vs[(kc + lm_r) * HST + ntp * 16 + lm_c];
                unsigned saddr = (unsigned)__cvta_generic_to_shared(src);
                asm volatile(
                    "ldmatrix.sync.aligned.m8n8.x4.trans.shared.b16 "
                    "{%0,%1,%2,%3}, [%4];"
                    : "=r"(v0), "=r"(v1), "=r"(v2), "=r"(v3) : "r"(saddr));
                mma_f16(oacc[2*ntp][0], oacc[2*ntp][1], oacc[2*ntp][2], oacc[2*ntp][3],
                        pa[ks][0], pa[ks][1], pa[ks][2], pa[ks][3], v0, v1);
                mma_f16(oacc[2*ntp+1][0], oacc[2*ntp+1][1], oacc[2*ntp+1][2], oacc[2*ntp+1][3],
                        pa[ks][0], pa[ks][1], pa[ks][2], pa[ks][3], v2, v3);
            }
        }
    }

    // ---- epilogue: normalize and store own rows directly ----
    float inv0 = 1.f / l0, inv1 = 1.f / l1;
    int r0 = q0 + sr0;
    int r1 = q0 + sr1;
    #pragma unroll
    for (int nt = 0; nt < 8; nt++) {
        int col = h * HD + nt * 8 + 2 * q;
        if (r0 < NN) {
            float2 v = make_float2(oacc[nt][0] * inv0, oacc[nt][1] * inv0);
            *(float2*)(CTX + ((long long)(b * NN + r0)) * DD + col) = v;
        }
        if (r1 < NN) {
            float2 v = make_float2(oacc[nt][2] * inv1, oacc[nt][3] * inv1);
            *(float2*)(CTX + ((long long)(b * NN + r1)) * DD + col) = v;
        }
    }
}

// ---------------------------------------------------------------------------
extern "C" void kernel_launch(void* const* d_in, const int* in_sizes, int n_in,
                              void* d_out, int out_size)
{
    const float* X    = (const float*)d_in[0];
    const float* sinp = (const float*)d_in[1];
    const float* cosp = (const float*)d_in[2];
    const float* Wq   = (const float*)d_in[3];
    const float* bq   = (const float*)d_in[4];
    const float* Wk   = (const float*)d_in[5];
    const float* bk   = (const float*)d_in[6];
    const float* Wv   = (const float*)d_in[7];
    const float* bv   = (const float*)d_in[8];
    const float* Wo   = (const float*)d_in[9];
    const float* bo   = (const float*)d_in[10];
    float* OUT = (float*)d_out;

    float *Qb, *Kb, *Vb, *CTX;
    cudaGetSymbolAddress((void**)&Qb,  g_Q);
    cudaGetSymbolAddress((void**)&Kb,  g_K);
    cudaGetSymbolAddress((void**)&Vb,  g_V);
    cudaGetSymbolAddress((void**)&CTX, g_CTX);

    cudaFuncSetAttribute(gemm_f16<0>,
                         cudaFuncAttributeMaxDynamicSharedMemorySize, GEMM_SMEM0);
    cudaFuncSetAttribute(gemm_f16<1>,
                         cudaFuncAttributeMaxDynamicSharedMemorySize, GEMM_SMEM1);
    cudaFuncSetAttribute(flash_attn_tc,
                         cudaFuncAttributeMaxDynamicSharedMemorySize, FA_SMEM);

    dim3 ggrid(DD / 128, (MM + 127) / 128);
    dim3 gblk(256);

    // Q/K projections with fused RoPE+transpose -> [B,H,N,HD]
    gemm_f16<1><<<ggrid, gblk, GEMM_SMEM1>>>(X, Wq, bq, Qb, MM, sinp, cosp);
    gemm_f16<1><<<ggrid, gblk, GEMM_SMEM1>>>(X, Wk, bk, Kb, MM, sinp, cosp);
    // V projection (stays in [B,N,H*HD]; attention reads it directly)
    gemm_f16<0><<<ggrid, gblk, GEMM_SMEM0>>>(X, Wv, bv, Vb, MM, sinp, cosp);

    // fp16 tensor-core attention
    dim3 agrid((NN + 127) / 128, HH, BB);   // (9,16,16)
    flash_attn_tc<<<agrid, 256, FA_SMEM>>>(Qb, Kb, Vb, CTX);

    // output projection straight into d_out
    gemm_f16<0><<<ggrid, gblk, GEMM_SMEM0>>>(CTX, Wo, bo, OUT, MM, sinp, cosp);
}

// round 16
// speedup vs baseline: 1.9207x; 1.0456x over previous
#include <cuda_runtime.h>
#include <cuda_fp16.h>
#include <cuda_bf16.h>

// Problem constants
#define BB   16
#define NN   1029
#define HH   16
#define HD   64
#define DD   1024
#define MM   (BB * NN)          // 16464
#define PREFIX 5                // N - NP
#define TOTAL  (MM * DD)        // 16859136

// Scratch (allocation-free rule: use __device__ globals)
// Q/K/V hold fp16 now; CTX stays fp32 (input to the O-projection GEMM).
__device__ __half g_Qh [TOTAL];
__device__ __half g_Kh [TOTAL];
__device__ __half g_Vh [TOTAL];
__device__ float  g_CTX[TOTAL];

__device__ __forceinline__ void mma_f16(
    float& c0, float& c1, float& c2, float& c3,
    unsigned a0, unsigned a1, unsigned a2, unsigned a3,
    unsigned b0, unsigned b1)
{
    asm volatile(
        "mma.sync.aligned.m16n8k16.row.col.f32.f16.f16.f32 "
        "{%0,%1,%2,%3}, {%4,%5,%6,%7}, {%8,%9}, {%0,%1,%2,%3};\n"
        : "+f"(c0), "+f"(c1), "+f"(c2), "+f"(c3)
        : "r"(a0), "r"(a1), "r"(a2), "r"(a3), "r"(b0), "r"(b1));
}

__device__ __forceinline__ void ldsm_x4(
    unsigned& r0, unsigned& r1, unsigned& r2, unsigned& r3, const __half* src)
{
    unsigned saddr = (unsigned)__cvta_generic_to_shared(src);
    asm volatile(
        "ldmatrix.sync.aligned.m8n8.x4.shared.b16 {%0,%1,%2,%3}, [%4];"
        : "=r"(r0), "=r"(r1), "=r"(r2), "=r"(r3) : "r"(saddr));
}

__device__ __forceinline__ unsigned packh2(float x, float y) {
    __half2 h = __floats2half2_rn(x, y);
    return *(unsigned*)&h;
}

__device__ __forceinline__ void cp_async16(const __half* dst, const void* src, int szbytes) {
    unsigned saddr = (unsigned)__cvta_generic_to_shared(dst);
    asm volatile("cp.async.cg.shared.global [%0], [%1], 16, %2;"
                 :: "r"(saddr), "l"(src), "r"(szbytes));
}
#define CP_COMMIT() asm volatile("cp.async.commit_group;")
#define CP_WAIT0()  asm volatile("cp.async.wait_group 0;" ::: "memory")

// ---------------------------------------------------------------------------
// FP16 tensor-core GEMM NT: C[m,n] = sum_k A[m,k] * W[n,k] + bias[n]
// Double-buffered smem; fragments via ldmatrix.x4.
// MODE 0: fp32 row-major store (final O projection).
// MODE 1: fp16 RoPE + transpose store to [B,H,N,HD] (Q/K; oscale applied).
// MODE 2: fp16 row-major store (V).
// ---------------------------------------------------------------------------
#define KH    40
#define STG   (128 * KH)
#define CPAD  132
#define GEMM_SMEM0 (4 * STG * 2)            // 40960 B
#define GEMM_SMEM1 (128 * CPAD * 4)         // 67584 B

template <int MODE>
__global__ __launch_bounds__(256) void gemm_f16(
    const float* __restrict__ A, const float* __restrict__ W,
    const float* __restrict__ bias, void* __restrict__ Cout, int M,
    const float* __restrict__ sinp, const float* __restrict__ cosp,
    float oscale)
{
    extern __shared__ __align__(16) unsigned char smem_raw[];
    __half* Abuf = (__half*)smem_raw;       // 2 x 128 x KH
    __half* Wbuf = Abuf + 2 * STG;          // 2 x 128 x KH

    const int tid  = threadIdx.x;
    const int warp = tid >> 5;
    const int lane = tid & 31;
    const int g    = lane >> 2;
    const int q    = lane & 3;
    const int wm   = warp >> 2;
    const int wn   = warp & 3;
    const int row0 = blockIdx.y * 128;
    const int col0 = blockIdx.x * 128;

    const int lmA_r = (lane & 7) + ((lane >> 3) & 1) * 8;
    const int lmA_k = ((lane >> 4) & 1) * 8;
    const int lmB_r = (lane & 7) + ((lane >> 4) & 1) * 8;
    const int lmB_k = ((lane >> 3) & 1) * 8;

    float acc[4][4][4];
    #pragma unroll
    for (int mt = 0; mt < 4; mt++)
        #pragma unroll
        for (int nt = 0; nt < 4; nt++)
            #pragma unroll
            for (int i = 0; i < 4; i++) acc[mt][nt][i] = 0.f;

    int lrow[4], lk[4];
    #pragma unroll
    for (int j = 0; j < 4; j++) {
        int idx = tid + j * 256;
        lrow[j] = idx >> 3;
        lk[j]   = (idx & 7) * 4;
    }
    const bool arow_ok[4] = {
        row0 + lrow[0] < M, row0 + lrow[1] < M,
        row0 + lrow[2] < M, row0 + lrow[3] < M };
    const float* Ap[4];
    const float* Wp[4];
    #pragma unroll
    for (int j = 0; j < 4; j++) {
        Ap[j] = A + (long long)(row0 + lrow[j]) * DD + lk[j];
        Wp[j] = W + (long long)(col0 + lrow[j]) * DD + lk[j];
    }

    const float4 z4 = make_float4(0.f, 0.f, 0.f, 0.f);
    float4 pa[4], pw[4];

    #pragma unroll
    for (int j = 0; j < 4; j++) {
        pa[j] = arow_ok[j] ? *(const float4*)(Ap[j]) : z4;
        pw[j] = *(const float4*)(Wp[j]);
    }
    #pragma unroll
    for (int j = 0; j < 4; j++) {
        __half2* as = (__half2*)&Abuf[lrow[j] * KH + lk[j]];
        as[0] = __floats2half2_rn(pa[j].x, pa[j].y);
        as[1] = __floats2half2_rn(pa[j].z, pa[j].w);
        __half2* ws = (__half2*)&Wbuf[lrow[j] * KH + lk[j]];
        ws[0] = __floats2half2_rn(pw[j].x, pw[j].y);
        ws[1] = __floats2half2_rn(pw[j].z, pw[j].w);
    }
    __syncthreads();
    #pragma unroll
    for (int j = 0; j < 4; j++) {
        pa[j] = arow_ok[j] ? *(const float4*)(Ap[j] + 32) : z4;
        pw[j] = *(const float4*)(Wp[j] + 32);
    }

    for (int c = 0; c < DD / 32; c++) {
        const __half* Asm = Abuf + (c & 1) * STG;
        const __half* Wsm = Wbuf + (c & 1) * STG;

        #pragma unroll
        for (int ks = 0; ks < 2; ks++) {
            const int kc = ks * 16;
            unsigned af[4][4], bf[4][2];
            #pragma unroll
            for (int mt = 0; mt < 4; mt++) {
                ldsm_x4(af[mt][0], af[mt][1], af[mt][2], af[mt][3],
                        &Asm[(wm * 64 + mt * 16 + lmA_r) * KH + kc + lmA_k]);
            }
            #pragma unroll
            for (int p = 0; p < 2; p++) {
                ldsm_x4(bf[2*p][0], bf[2*p][1], bf[2*p+1][0], bf[2*p+1][1],
                        &Wsm[(wn * 32 + p * 16 + lmB_r) * KH + kc + lmB_k]);
            }
            #pragma unroll
            for (int mt = 0; mt < 4; mt++)
                #pragma unroll
                for (int nt = 0; nt < 4; nt++)
                    mma_f16(acc[mt][nt][0], acc[mt][nt][1],
                            acc[mt][nt][2], acc[mt][nt][3],
                            af[mt][0], af[mt][1], af[mt][2], af[mt][3],
                            bf[nt][0], bf[nt][1]);
        }

        if (c + 1 < DD / 32) {
            __half* Ad = Abuf + ((c + 1) & 1) * STG;
            __half* Wd = Wbuf + ((c + 1) & 1) * STG;
            #pragma unroll
            for (int j = 0; j < 4; j++) {
                __half2* as = (__half2*)&Ad[lrow[j] * KH + lk[j]];
                as[0] = __floats2half2_rn(pa[j].x, pa[j].y);
                as[1] = __floats2half2_rn(pa[j].z, pa[j].w);
                __half2* ws = (__half2*)&Wd[lrow[j] * KH + lk[j]];
                ws[0] = __floats2half2_rn(pw[j].x, pw[j].y);
                ws[1] = __floats2half2_rn(pw[j].z, pw[j].w);
            }
        }
        if (c + 2 < DD / 32) {
            int kb = (c + 2) * 32;
            #pragma unroll
            for (int j = 0; j < 4; j++) {
                pa[j] = arow_ok[j] ? *(const float4*)(Ap[j] + kb) : z4;
                pw[j] = *(const float4*)(Wp[j] + kb);
            }
        }
        __syncthreads();
    }

    if (MODE == 0) {
        float* C = (float*)Cout;
        #pragma unroll
        for (int mt = 0; mt < 4; mt++) {
            int r0 = row0 + wm * 64 + mt * 16 + g;
            int r1 = r0 + 8;
            #pragma unroll
            for (int nt = 0; nt < 4; nt++) {
                int c = col0 + wn * 32 + nt * 8 + 2 * q;
                float bx = bias[c], by = bias[c + 1];
                if (r0 < M) {
                    float2 v = make_float2(acc[mt][nt][0] + bx, acc[mt][nt][1] + by);
                    *(float2*)(C + (long long)r0 * DD + c) = v;
                }
                if (r1 < M) {
                    float2 v = make_float2(acc[mt][nt][2] + bx, acc[mt][nt][3] + by);
                    *(float2*)(C + (long long)r1 * DD + c) = v;
                }
            }
        }
    } else if (MODE == 2) {
        __half* C = (__half*)Cout;
        #pragma unroll
        for (int mt = 0; mt < 4; mt++) {
            int r0 = row0 + wm * 64 + mt * 16 + g;
            int r1 = r0 + 8;
            #pragma unroll
            for (int nt = 0; nt < 4; nt++) {
                int c = col0 + wn * 32 + nt * 8 + 2 * q;
                float bx = bias[c], by = bias[c + 1];
                if (r0 < M)
                    *(__half2*)(C + (long long)r0 * DD + c) =
                        __floats2half2_rn(acc[mt][nt][0] + bx, acc[mt][nt][1] + by);
                if (r1 < M)
                    *(__half2*)(C + (long long)r1 * DD + c) =
                        __floats2half2_rn(acc[mt][nt][2] + bx, acc[mt][nt][3] + by);
            }
        }
    } else {
        // MODE 1: stage fp32 (bias applied), then RoPE + transpose fp16 store
        __half* C = (__half*)Cout;
        float* Cs = (float*)smem_raw;   // 128 x CPAD
        #pragma unroll
        for (int mt = 0; mt < 4; mt++) {
            int lr0 = wm * 64 + mt * 16 + g;
            int lr1 = lr0 + 8;
            #pragma unroll
            for (int nt = 0; nt < 4; nt++) {
                int lc = wn * 32 + nt * 8 + 2 * q;
                float bx = bias[col0 + lc], by = bias[col0 + lc + 1];
                *(float2*)&Cs[lr0 * CPAD + lc] =
                    make_float2(acc[mt][nt][0] + bx, acc[mt][nt][1] + by);
                *(float2*)&Cs[lr1 * CPAD + lc] =
                    make_float2(acc[mt][nt][2] + bx, acc[mt][nt][3] + by);
            }
        }
        __syncthreads();

        #pragma unroll
        for (int i = 0; i < 16; i++) {
            int idx = tid + i * 256;
            int row = idx >> 5;
            int c4  = (idx & 31) * 4;
            int R = row0 + row;
            if (R >= M) continue;
            int b = R / NN;
            int t = R - b * NN;
            int gcol = col0 + c4;
            int h = gcol >> 6;
            int d = gcol & 63;

            float4 x = *(float4*)&Cs[row * CPAD + c4];
            float4 v = x;
            if (t >= PREFIX) {
                int pos = t - PREFIX;
                float4 cc = *(const float4*)(cosp + pos * HD + d);
                float4 ss = *(const float4*)(sinp + pos * HD + d);
                float4 xo = *(float4*)&Cs[row * CPAD + (c4 ^ 32)];
                if (d < 32) { xo.x = -xo.x; xo.y = -xo.y; xo.z = -xo.z; xo.w = -xo.w; }
                v.x = x.x * cc.x + xo.x * ss.x;
                v.y = x.y * cc.y + xo.y * ss.y;
                v.z = x.z * cc.z + xo.z * ss.z;
                v.w = x.w * cc.w + xo.w * ss.w;
            }
            __half2 h0 = __floats2half2_rn(v.x * oscale, v.y * oscale);
            __half2 h1 = __floats2half2_rn(v.z * oscale, v.w * oscale);
            uint2 pk = make_uint2(*(unsigned*)&h0, *(unsigned*)&h1);
            *(uint2*)(C + (((long long)(b * HH + h)) * NN + t) * HD + d) = pk;
        }
    }
}

// ---------------------------------------------------------------------------
// FP16 flash attention v4: fp16 inputs, cp.async double-buffered K/V tiles,
// register-resident P; one __syncthreads per kv tile.
// Q: [B,H,N,HD] fp16 pre-scaled by HD^-0.5.  K: [B,H,N,HD] fp16.
// V: [B,N,H*HD] fp16.  CTX out: [B,N,H*HD] fp32.
// ---------------------------------------------------------------------------
#define HST 72
#define FA_SMEM ((128 * HST + 4 * 64 * HST) * 2)   // 55296 B

__global__ __launch_bounds__(256, 2) void flash_attn_tc(
    const __half* __restrict__ Q, const __half* __restrict__ K,
    const __half* __restrict__ Vy, float* __restrict__ CTX)
{
    extern __shared__ __half sm_h[];
    __half* Qs  = sm_h;                     // 128 x HST
    __half* Kb0 = Qs + 128 * HST;           // 64 x HST
    __half* Vb0 = Kb0 + 64 * HST;           // 64 x HST
    __half* Kb1 = Vb0 + 64 * HST;           // 64 x HST
    __half* Vb1 = Kb1 + 64 * HST;           // 64 x HST

    const int q0 = blockIdx.x * 128;
    const int h  = blockIdx.y;
    const int b  = blockIdx.z;
    const long long baseQ = ((long long)(b * HH + h)) * NN * HD;
    const int tid  = threadIdx.x;
    const int warp = tid >> 5;
    const int lane = tid & 31;
    const int g    = lane >> 2;
    const int q    = lane & 3;
    const int sr0  = warp * 16 + g;
    const int sr1  = sr0 + 8;

    const int lmB_r = (lane & 7) + ((lane >> 4) & 1) * 8;
    const int lmB_k = ((lane >> 3) & 1) * 8;
    const int lm_r  = lane & 15;
    const int lm_c  = (lane >> 4) * 8;

    // kv tile loader: 64 rows x 64 halves x2 tensors = 1024 x 16B / 256 thr
    const int lrow = (tid * 2) >> 3;        // two segs per thread per tensor
    const int lseg = (tid * 2) & 7;

    // ---- prologue: Q tile + kv tile 0 via cp.async ----
    #pragma unroll
    for (int i = 0; i < 4; i++) {
        int idx = tid + i * 256;
        int row = idx >> 3, seg = idx & 7;
        int r = q0 + row;
        int rc = (r < NN) ? r : (NN - 1);
        cp_async16(&Qs[row * HST + seg * 8],
                   Q + baseQ + (long long)rc * HD + seg * 8,
                   (r < NN) ? 16 : 0);
    }
    {
        int kv = lrow;          // tile 0
        int sz = (kv < NN) ? 16 : 0;
        const __half* kr = K + baseQ + (long long)kv * HD;
        const __half* vr = Vy + ((long long)(b * NN + kv)) * DD + h * HD;
        cp_async16(&Kb0[lrow * HST + lseg * 8], kr + lseg * 8, sz);
        cp_async16(&Kb0[lrow * HST + (lseg + 1) * 8], kr + (lseg + 1) * 8, sz);
        cp_async16(&Vb0[lrow * HST + lseg * 8], vr + lseg * 8, sz);
        cp_async16(&Vb0[lrow * HST + (lseg + 1) * 8], vr + (lseg + 1) * 8, sz);
    }
    CP_COMMIT();
    CP_WAIT0();
    __syncthreads();

    // hoist Q fragments (tile-invariant)
    unsigned qa[4][4];
    {
        const int lmA_r = (lane & 7) + ((lane >> 3) & 1) * 8;
        const int lmA_k = ((lane >> 4) & 1) * 8;
        #pragma unroll
        for (int ks = 0; ks < 4; ks++)
            ldsm_x4(qa[ks][0], qa[ks][1], qa[ks][2], qa[ks][3],
                    &Qs[(warp * 16 + lmA_r) * HST + ks * 16 + lmA_k]);
    }

    float m0 = -1e30f, m1 = -1e30f, l0 = 0.f, l1 = 0.f;
    float oacc[8][4];
    #pragma unroll
    for (int nt = 0; nt < 8; nt++)
        #pragma unroll
        for (int i = 0; i < 4; i++) oacc[nt][i] = 0.f;

    const int T = (NN + 63) / 64;   // 17
    for (int t = 0; t < T; t++) {
        const int k0 = t * 64;
        const __half* Ks = (t & 1) ? Kb1 : Kb0;
        const __half* Vs = (t & 1) ? Vb1 : Vb0;

        // issue cp.async for tile t+1 into the other buffer
        if (t + 1 < T) {
            __half* Kd = (t & 1) ? Kb0 : Kb1;
            __half* Vd = (t & 1) ? Vb0 : Vb1;
            int kv = k0 + 64 + lrow;
            int kc2 = (kv < NN) ? kv : (NN - 1);
            int sz = (kv < NN) ? 16 : 0;
            const __half* kr = K + baseQ + (long long)kc2 * HD;
            const __half* vr = Vy + ((long long)(b * NN + kc2)) * DD + h * HD;
            cp_async16(&Kd[lrow * HST + lseg * 8], kr + lseg * 8, sz);
            cp_async16(&Kd[lrow * HST + (lseg + 1) * 8], kr + (lseg + 1) * 8, sz);
            cp_async16(&Vd[lrow * HST + lseg * 8], vr + lseg * 8, sz);
            cp_async16(&Vd[lrow * HST + (lseg + 1) * 8], vr + (lseg + 1) * 8, sz);
            CP_COMMIT();
        }

        // ---- S = Q @ K^T (16q x 64kv per warp) ----
        float sacc[8][4];
        #pragma unroll
        for (int nt = 0; nt < 8; nt++)
            #pragma unroll
            for (int i = 0; i < 4; i++) sacc[nt][i] = 0.f;

        #pragma unroll
        for (int ks = 0; ks < 4; ks++) {
            const int kc = ks * 16;
            #pragma unroll
            for (int p = 0; p < 4; p++) {
                unsigned b0, b1, b2, b3;
                ldsm_x4(b0, b1, b2, b3,
                        &Ks[(p * 16 + lmB_r) * HST + kc + lmB_k]);
                mma_f16(sacc[2*p][0], sacc[2*p][1], sacc[2*p][2], sacc[2*p][3],
                        qa[ks][0], qa[ks][1], qa[ks][2], qa[ks][3], b0, b1);
                mma_f16(sacc[2*p+1][0], sacc[2*p+1][1], sacc[2*p+1][2], sacc[2*p+1][3],
                        qa[ks][0], qa[ks][1], qa[ks][2], qa[ks][3], b2, b3);
            }
        }

        if (k0 + 64 > NN) {
            #pragma unroll
            for (int nt = 0; nt < 8; nt++) {
                int c = k0 + nt * 8 + 2 * q;
                if (c >= NN)     { sacc[nt][0] = -1e30f; sacc[nt][2] = -1e30f; }
                if (c + 1 >= NN) { sacc[nt][1] = -1e30f; sacc[nt][3] = -1e30f; }
            }
        }

        // ---- online softmax ----
        float t0 = -1e30f, t1 = -1e30f;
        #pragma unroll
        for (int nt = 0; nt < 8; nt++) {
            t0 = fmaxf(t0, fmaxf(sacc[nt][0], sacc[nt][1]));
            t1 = fmaxf(t1, fmaxf(sacc[nt][2], sacc[nt][3]));
        }
        t0 = fmaxf(t0, __shfl_xor_sync(0xffffffffu, t0, 1));
        t0 = fmaxf(t0, __shfl_xor_sync(0xffffffffu, t0, 2));
        t1 = fmaxf(t1, __shfl_xor_sync(0xffffffffu, t1, 1));
        t1 = fmaxf(t1, __shfl_xor_sync(0xffffffffu, t1, 2));
        float mn0 = fmaxf(m0, t0), mn1 = fmaxf(m1, t1);
        float sc0 = __expf(m0 - mn0), sc1 = __expf(m1 - mn1);
        m0 = mn0; m1 = mn1;

        unsigned pa[4][4];
        float ls0 = 0.f, ls1 = 0.f;
        #pragma unroll
        for (int nt = 0; nt < 8; nt++) {
            float p0 = __expf(sacc[nt][0] - mn0);
            float p1 = __expf(sacc[nt][1] - mn0);
            float p2 = __expf(sacc[nt][2] - mn1);
            float p3 = __expf(sacc[nt][3] - mn1);
            ls0 += p0 + p1;
            ls1 += p2 + p3;
            if ((nt & 1) == 0) {
                pa[nt >> 1][0] = packh2(p0, p1);
                pa[nt >> 1][1] = packh2(p2, p3);
            } else {
                pa[nt >> 1][2] = packh2(p0, p1);
                pa[nt >> 1][3] = packh2(p2, p3);
            }
        }
        ls0 += __shfl_xor_sync(0xffffffffu, ls0, 1);
        ls0 += __shfl_xor_sync(0xffffffffu, ls0, 2);
        ls1 += __shfl_xor_sync(0xffffffffu, ls1, 1);
        ls1 += __shfl_xor_sync(0xffffffffu, ls1, 2);
        l0 = l0 * sc0 + ls0;
        l1 = l1 * sc1 + ls1;

        #pragma unroll
        for (int nt = 0; nt < 8; nt++) {
            oacc[nt][0] *= sc0; oacc[nt][1] *= sc0;
            oacc[nt][2] *= sc1; oacc[nt][3] *= sc1;
        }

        // ---- PV: O[16q x 64d] += P @ V ----
        #pragma unroll
        for (int ks = 0; ks < 4; ks++) {
            const int kc = ks * 16;
            #pragma unroll
            for (int ntp = 0; ntp < 4; ntp++) {
                unsigned v0, v1, v2, v3;
                const __half* src = &Vs[(kc + lm_r) * HST + ntp * 16 + lm_c];
                unsigned saddr = (unsigned)__cvta_generic_to_shared(src);
                asm volatile(
                    "ldmatrix.sync.aligned.m8n8.x4.trans.shared.b16 "
                    "{%0,%1,%2,%3}, [%4];"
                    : "=r"(v0), "=r"(v1), "=r"(v2), "=r"(v3) : "r"(saddr));
                mma_f16(oacc[2*ntp][0], oacc[2*ntp][1], oacc[2*ntp][2], oacc[2*ntp][3],
                        pa[ks][0], pa[ks][1], pa[ks][2], pa[ks][3], v0, v1);
                mma_f16(oacc[2*ntp+1][0], oacc[2*ntp+1][1], oacc[2*ntp+1][2], oacc[2*ntp+1][3],
                        pa[ks][0], pa[ks][1], pa[ks][2], pa[ks][3], v2, v3);
            }
        }

        CP_WAIT0();
        __syncthreads();
    }

    // ---- epilogue: normalize and store own rows ----
    float inv0 = 1.f / l0, inv1 = 1.f / l1;
    int r0 = q0 + sr0;
    int r1 = q0 + sr1;
    #pragma unroll
    for (int nt = 0; nt < 8; nt++) {
        int col = h * HD + nt * 8 + 2 * q;
        if (r0 < NN) {
            float2 v = make_float2(oacc[nt][0] * inv0, oacc[nt][1] * inv0);
            *(float2*)(CTX + ((long long)(b * NN + r0)) * DD + col) = v;
        }
        if (r1 < NN) {
            float2 v = make_float2(oacc[nt][2] * inv1, oacc[nt][3] * inv1);
            *(float2*)(CTX + ((long long)(b * NN + r1)) * DD + col) = v;
        }
    }
}

// ---------------------------------------------------------------------------
extern "C" void kernel_launch(void* const* d_in, const int* in_sizes, int n_in,
                              void* d_out, int out_size)
{
    const float* X    = (const float*)d_in[0];
    const float* sinp = (const float*)d_in[1];
    const float* cosp = (const float*)d_in[2];
    const float* Wq   = (const float*)d_in[3];
    const float* bq   = (const float*)d_in[4];
    const float* Wk   = (const float*)d_in[5];
    const float* bk   = (const float*)d_in[6];
    const float* Wv   = (const float*)d_in[7];
    const float* bv   = (const float*)d_in[8];
    const float* Wo   = (const float*)d_in[9];
    const float* bo   = (const float*)d_in[10];
    float* OUT = (float*)d_out;

    __half *Qh, *Kh, *Vh;
    float *CTX;
    cudaGetSymbolAddress((void**)&Qh,  g_Qh);
    cudaGetSymbolAddress((void**)&Kh,  g_Kh);
    cudaGetSymbolAddress((void**)&Vh,  g_Vh);
    cudaGetSymbolAddress((void**)&CTX, g_CTX);

    cudaFuncSetAttribute(gemm_f16<0>,
                         cudaFuncAttributeMaxDynamicSharedMemorySize, GEMM_SMEM0);
    cudaFuncSetAttribute(gemm_f16<1>,
                         cudaFuncAttributeMaxDynamicSharedMemorySize, GEMM_SMEM1);
    cudaFuncSetAttribute(gemm_f16<2>,
                         cudaFuncAttributeMaxDynamicSharedMemorySize, GEMM_SMEM0);
    cudaFuncSetAttribute(flash_attn_tc,
                         cudaFuncAttributeMaxDynamicSharedMemorySize, FA_SMEM);

    dim3 ggrid(DD / 128, (MM + 127) / 128);
    dim3 gblk(256);

    // Q/K projections: fused RoPE + transpose, fp16 out (Q pre-scaled)
    gemm_f16<1><<<ggrid, gblk, GEMM_SMEM1>>>(X, Wq, bq, Qh, MM, sinp, cosp, 0.125f);
    gemm_f16<1><<<ggrid, gblk, GEMM_SMEM1>>>(X, Wk, bk, Kh, MM, sinp, cosp, 1.0f);
    // V projection: fp16 out, [B,N,H*HD]
    gemm_f16<2><<<ggrid, gblk, GEMM_SMEM0>>>(X, Wv, bv, Vh, MM, sinp, cosp, 1.0f);

    // fp16 attention with cp.async pipeline
    dim3 agrid((NN + 127) / 128, HH, BB);   // (9,16,16)
    flash_attn_tc<<<agrid, 256, FA_SMEM>>>(Qh, Kh, Vh, CTX);

    // output projection (fp32 in/out) straight into d_out
    gemm_f16<0><<<ggrid, gblk, GEMM_SMEM0>>>(CTX, Wo, bo, OUT, MM, sinp, cosp, 1.0f);
}